// round 9
// baseline (speedup 1.0000x reference)
#include <cuda_runtime.h>
#include <cuda_bf16.h>
#include <mma.h>
#include <cstdint>

using namespace nvcuda;

#define BSZ 8
#define HID 64
#define NV  1024
#define NT  64
#define TN  32     // n-tile (nodes per CTA)

// bf16 hi/lo split state [buf][(b*64+hid)*NV + v]
__device__ __nv_bfloat16 g_hh[2][BSZ * HID * NV];
__device__ __nv_bfloat16 g_hl[2][BSZ * HID * NV];
__device__ __nv_bfloat16 g_gh[NV * NV];       // graph hi  [w][v]
__device__ __nv_bfloat16 g_gl[NV * NV];       // graph lo
__device__ __nv_bfloat16 g_whh_h[192 * 64];   // W_hh hi [gate][hid]
__device__ __nv_bfloat16 g_whh_l[192 * 64];
__device__ float g_xh[BSZ][NV];
__device__ int   g_mask_mode;                 // 0=byte, 1=int32, 2=float32

// smem byte offsets
#define OFF_AH(b) ((b) * 9216)                // 2 x [64m][72] bf16
#define OFF_AL(b) (18432 + (b) * 9216)
#define OFF_BH(b) (36864 + (b) * 4608)        // 2 x [32n][72] bf16
#define OFF_BL(b) (46080 + (b) * 4608)
#define OFF_HD   0          // f32 [64][40]  (aliases AH)
#define OFF_HDH  18432      // bf16 [64][40] (aliases AL)
#define OFF_HDL  23552
#define OFF_GD   55296      // f32 [192][40] = 30720
#define OFF_HN   86016      // f32 [64][40]  = 10240
#define OFF_XG   96256      // f32 [32]
#define OFF_PART 96384      // f32 [512]
#define OFF_SX   98432      // f32 [32]
#define OFF_SMK  98560      // f32 [32]
#define SMEM_TOTAL 98688

// ---------------------------------------------------------------------------
__device__ __forceinline__ void cp_async16(uint32_t s, const void* g) {
    asm volatile("cp.async.ca.shared.global [%0], [%1], 16;" :: "r"(s), "l"(g));
}
__device__ __forceinline__ void cp_commit() { asm volatile("cp.async.commit_group;"); }
__device__ __forceinline__ void cp_wait0()  { asm volatile("cp.async.wait_group 0;"); }
__device__ __forceinline__ void cp_wait1()  { asm volatile("cp.async.wait_group 1;"); }
__device__ __forceinline__ void stcs(float* p, float v) {
    asm volatile("st.global.cs.f32 [%0], %1;" :: "l"(p), "f"(v));
}
__device__ __forceinline__ float tanh_fast(float x) {
    float y;
    asm("tanh.approx.f32 %0, %1;" : "=f"(y) : "f"(x));
    return y;
}

// ---------------------------------------------------------------------------
__global__ void detect_mask_kernel(const unsigned int* __restrict__ m) {
    __shared__ int viol_i, viol_f;
    if (threadIdx.x == 0) { viol_i = 0; viol_f = 0; }
    __syncthreads();
    int li = 0, lf = 0;
    const int nwords = (BSZ * NV * NT) / 4;
    for (int i = threadIdx.x; i < nwords; i += blockDim.x) {
        unsigned int w = m[i];
        if (w > 1u) li = 1;
        if (w != 0u && w != 0x3F800000u) lf = 1;
    }
    if (li) atomicOr(&viol_i, 1);
    if (lf) atomicOr(&viol_f, 1);
    __syncthreads();
    if (threadIdx.x == 0)
        g_mask_mode = (!viol_f) ? 2 : ((!viol_i) ? 1 : 0);
}

// Merged one-time setup: graph split, W_hh split, h0 init.
__global__ void setup_kernel(const float* __restrict__ graph,
                             const float* __restrict__ W_hh,
                             const float* __restrict__ h0) {
    int i = blockIdx.x * blockDim.x + threadIdx.x;
    {
        float v = graph[i];
        __nv_bfloat16 hi = __float2bfloat16(v);
        g_gh[i] = hi;
        g_gl[i] = __float2bfloat16(v - __bfloat162float(hi));
    }
    if (i < 192 * 64) {
        float v = W_hh[i];
        __nv_bfloat16 hi = __float2bfloat16(v);
        g_whh_h[i] = hi;
        g_whh_l[i] = __float2bfloat16(v - __bfloat162float(hi));
    }
    if (i < BSZ * HID * NV) {
        int v  = i & (NV - 1);
        int hh = (i >> 10) & 63;
        float val = h0[hh * NV + v];
        __nv_bfloat16 hi = __float2bfloat16(val);
        g_hh[0][i] = hi;
        g_hl[0][i] = __float2bfloat16(val - __bfloat162float(hi));
    }
}

// t=0 prep from h0 directly. Grid (4, 8), 256 threads.
__global__ void prep_kernel(
    const float* __restrict__ x, const unsigned char* __restrict__ mask_raw,
    const float* __restrict__ h0,
    const float* __restrict__ W_init, const float* __restrict__ b_init,
    float* __restrict__ out_preds)
{
    int b = blockIdx.y;
    int v = blockIdx.x * 256 + threadIdx.x;
    float d = 0.f;
    #pragma unroll 16
    for (int hh = 0; hh < HID; hh++) d += W_init[hh] * h0[hh * NV + v];
    d += b_init[0];
    int xi = (b * NV + v) * NT + 0;
    int mode = g_mask_mode;
    bool m;
    if (mode == 0)      m = mask_raw[xi] != 0;
    else if (mode == 1) m = ((const int*)mask_raw)[xi] != 0;
    else                m = ((const float*)mask_raw)[xi] != 0.f;
    g_xh[b][v] = m ? x[xi] : d;
    out_preds[xi] = d;
}

// ---------------------------------------------------------------------------
// Step kernel: grid (32 w-tiles of 32, 8 batches) = 256 CTAs, 256 threads.
// 2 CTAs/SM — co-resident CTAs hide each other's phase latency.
// ---------------------------------------------------------------------------
__global__ void __launch_bounds__(256) step_tc_kernel(int t, int cur,
    const float* __restrict__ x, const unsigned char* __restrict__ mask_raw,
    const float* __restrict__ ind_graph,
    const float* __restrict__ W_init, const float* __restrict__ b_init,
    const float* __restrict__ W_out,  const float* __restrict__ b_out,
    const float* __restrict__ W_ih,
    const float* __restrict__ b_ih,   const float* __restrict__ b_hh,
    float* __restrict__ out_imps, float* __restrict__ out_preds,
    float* __restrict__ out_reprs)
{
    extern __shared__ __align__(32) char smem[];
    const uint32_t sbase = (uint32_t)__cvta_generic_to_shared(smem);

    const int tid  = threadIdx.x;
    const int wid  = tid >> 5;
    const int wt   = blockIdx.x;
    const int b    = blockIdx.y;          // batch == m-tile
    const int w0   = wt * TN;
    const int m0   = b * 64;
    const int nxt  = cur ^ 1;

    float* hd   = (float*)(smem + OFF_HD);
    __nv_bfloat16* hdh = (__nv_bfloat16*)(smem + OFF_HDH);
    __nv_bfloat16* hdl = (__nv_bfloat16*)(smem + OFF_HDL);
    float* gd   = (float*)(smem + OFF_GD);
    float* hn   = (float*)(smem + OFF_HN);
    float* xg   = (float*)(smem + OFF_XG);
    float* part = (float*)(smem + OFF_PART);
    float* sx   = (float*)(smem + OFF_SX);
    float* smk  = (float*)(smem + OFF_SMK);

    // fill(kt): cp.async A (64x64) + B (32x64) hi/lo bf16 tiles, ld=72.
    auto fill = [&](int kt) {
        int buf = kt & 1;
        int v0  = kt * 64;
        const __nv_bfloat16* Ah = g_hh[cur] + (size_t)m0 * NV + v0;
        const __nv_bfloat16* Al = g_hl[cur] + (size_t)m0 * NV + v0;
        const __nv_bfloat16* Bh = g_gh + (size_t)w0 * NV + v0;
        const __nv_bfloat16* Bl = g_gl + (size_t)w0 * NV + v0;
        const uint32_t dAh = sbase + OFF_AH(buf), dAl = sbase + OFF_AL(buf);
        const uint32_t dBh = sbase + OFF_BH(buf), dBl = sbase + OFF_BL(buf);
        // A: 512 chunks per matrix (2 per thread)
        #pragma unroll
        for (int i = 0; i < 2; i++) {
            int c = i * 256 + tid;
            int row = c >> 3, kc = c & 7;
            cp_async16(dAh + row * 144 + kc * 16, Ah + row * NV + kc * 8);
            cp_async16(dAl + row * 144 + kc * 16, Al + row * NV + kc * 8);
        }
        // B: 256 chunks per matrix (1 per thread)
        {
            int row = tid >> 3, kc = tid & 7;
            cp_async16(dBh + row * 144 + kc * 16, Bh + row * NV + kc * 8);
            cp_async16(dBl + row * 144 + kc * 16, Bl + row * NV + kc * 8);
        }
        cp_commit();
    };

    fill(0);

    // ---- prefetch x/mask for t+1 (overlapped) ----
    if (tid >= 224 && t < NT - 1) {
        int w = tid - 224;
        int xi = (b * NV + w0 + w) * NT + (t + 1);
        int mode = g_mask_mode;
        bool m;
        if (mode == 0)      m = mask_raw[xi] != 0;
        else if (mode == 1) m = ((const int*)mask_raw)[xi] != 0;
        else                m = ((const float*)mask_raw)[xi] != 0.f;
        smk[w] = m ? 1.f : 0.f;
        sx[w]  = x[xi];
    }

    // ---- x_g[w] = sum_v g_xh[b][v] * ind_graph[w0+w][v] (overlaps tile-0) ----
    {
        int w = tid & 31, q = tid >> 5;            // 8 chunks of 128 v
        const float4* ig = (const float4*)&ind_graph[(w0 + w) * NV + q * 128];
        const float4* xh = (const float4*)&g_xh[b][q * 128];
        float s = 0.f;
        #pragma unroll 8
        for (int j = 0; j < 32; j++) {
            float4 a = ig[j], c = xh[j];
            s += a.x * c.x + a.y * c.y + a.z * c.z + a.w * c.w;
        }
        part[q * 32 + w] = s;
    }
    __syncthreads();
    if (tid < TN) {
        float s = 0.f;
        #pragma unroll
        for (int q = 0; q < 8; q++) s += part[q * 32 + tid];
        xg[tid] = s;
    }

    // ---- GEMM: warp (wm = wid&3 -> m-tile, wn = wid>>2 -> n-tile) ----
    wmma::fragment<wmma::accumulator, 16, 16, 16, float> acc;
    wmma::fill_fragment(acc, 0.f);
    const int wm = wid & 3, wn = wid >> 2;

    for (int kt = 0; kt < 16; kt++) {
        if (kt < 15) { fill(kt + 1); cp_wait1(); } else { cp_wait0(); }
        __syncthreads();                         // buffer kt ready
        const int buf = kt & 1;
        const __nv_bfloat16* Ah = (const __nv_bfloat16*)(smem + OFF_AH(buf));
        const __nv_bfloat16* Al = (const __nv_bfloat16*)(smem + OFF_AL(buf));
        const __nv_bfloat16* Bh = (const __nv_bfloat16*)(smem + OFF_BH(buf));
        const __nv_bfloat16* Bl = (const __nv_bfloat16*)(smem + OFF_BL(buf));
        #pragma unroll
        for (int ks = 0; ks < 4; ks++) {
            wmma::fragment<wmma::matrix_a, 16, 16, 16, __nv_bfloat16, wmma::row_major> fah, fal;
            wmma::fragment<wmma::matrix_b, 16, 16, 16, __nv_bfloat16, wmma::col_major> fbh, fbl;
            wmma::load_matrix_sync(fah, Ah + wm * 16 * 72 + ks * 16, 72);
            wmma::load_matrix_sync(fal, Al + wm * 16 * 72 + ks * 16, 72);
            wmma::load_matrix_sync(fbh, Bh + wn * 16 * 72 + ks * 16, 72);
            wmma::load_matrix_sync(fbl, Bl + wn * 16 * 72 + ks * 16, 72);
            wmma::mma_sync(acc, fah, fbh, acc);
            wmma::mma_sync(acc, fah, fbl, acc);
            wmma::mma_sync(acc, fal, fbh, acc);
        }
        __syncthreads();                         // all reads done before refill
    }

    // ---- store h_diff (f32) into smem [64][40] (aliases dead buffers) ----
    wmma::store_matrix_sync(hd + wm * 16 * 40 + wn * 16, acc, 40, wmma::mem_row_major);
    __syncthreads();

    // ---- split h_diff -> bf16 hi/lo for the gate GEMM ----
    #pragma unroll
    for (int i = 0; i < 8; i++) {
        int idx = tid + i * 256;               // 2048
        int row = idx >> 5, col = idx & 31;
        float v = hd[row * 40 + col];
        __nv_bfloat16 hi = __float2bfloat16(v);
        hdh[row * 40 + col] = hi;
        hdl[row * 40 + col] = __float2bfloat16(v - __bfloat162float(hi));
    }
    __syncthreads();

    // ---- gates GEMM: gd[192 x 32] = W_hh · h_diff (A fragments from global) ----
    {
        #pragma unroll
        for (int i = 0; i < 3; i++) {
            int tile = wid * 3 + i;              // 24 tiles: gm 0..11, gn 0..1
            int gm = tile >> 1, gn = tile & 1;
            wmma::fragment<wmma::accumulator, 16, 16, 16, float> gacc;
            wmma::fill_fragment(gacc, 0.f);
            #pragma unroll
            for (int ks = 0; ks < 4; ks++) {
                wmma::fragment<wmma::matrix_a, 16, 16, 16, __nv_bfloat16, wmma::row_major> fah, fal;
                wmma::fragment<wmma::matrix_b, 16, 16, 16, __nv_bfloat16, wmma::row_major> gbh, gbl;
                int aoff = gm * 16 * 64 + ks * 16;
                int boff = ks * 16 * 40 + gn * 16;
                wmma::load_matrix_sync(fah, g_whh_h + aoff, 64);
                wmma::load_matrix_sync(fal, g_whh_l + aoff, 64);
                wmma::load_matrix_sync(gbh, hdh + boff, 40);
                wmma::load_matrix_sync(gbl, hdl + boff, 40);
                wmma::mma_sync(gacc, fah, gbh, gacc);
                wmma::mma_sync(gacc, fah, gbl, gacc);
                wmma::mma_sync(gacc, fal, gbh, gacc);
            }
            wmma::store_matrix_sync(gd + gm * 16 * 40 + gn * 16, gacc, 40,
                                    wmma::mem_row_major);
        }
    }
    __syncthreads();

    // ---- nonlinearity + state update: thread = (hh, wq), 8 nodes ----
    {
        const int hh = tid >> 2;
        const int wq = tid & 3;
        float wih_r = W_ih[hh],  wih_z = W_ih[64 + hh],  wih_n = W_ih[128 + hh];
        float bi_r  = b_ih[hh] + b_hh[hh];
        float bi_z  = b_ih[64 + hh] + b_hh[64 + hh];
        float bi_n  = b_ih[128 + hh];
        float bh_n  = b_hh[128 + hh];
        #pragma unroll
        for (int k = 0; k < 8; k++) {
            int w = wq + 4 * k;
            float ar = gd[hh * 40 + w];
            float az = gd[(64 + hh) * 40 + w];
            float an = gd[(128 + hh) * 40 + w];
            float xgv = xg[w];
            float r = 0.5f + 0.5f * tanh_fast(0.5f * (ar + wih_r * xgv + bi_r));
            float z = 0.5f + 0.5f * tanh_fast(0.5f * (az + wih_z * xgv + bi_z));
            float n = tanh_fast(wih_n * xgv + bi_n + r * (an + bh_n));
            float hd_self = hd[hh * 40 + w];
            float hnew = (1.f - z) * n + z * hd_self;
            size_t si = (size_t)(m0 + hh) * NV + w0 + w;
            __nv_bfloat16 hi = __float2bfloat16(hnew);
            g_hh[nxt][si] = hi;
            g_hl[nxt][si] = __float2bfloat16(hnew - __bfloat162float(hi));
            stcs(&out_reprs[((b * HID + hh) * NV + (w0 + w)) * NT + t], hnew);
            hn[hh * 40 + w] = hnew;
        }
    }
    __syncthreads();

    // ---- fused epilogue: imps(t), preds(t+1), g_xh(t+1) ----
    {
        int w = tid & 31, q = tid >> 5;           // q: 8 hid each
        float so = 0.f, si = 0.f;
        #pragma unroll
        for (int j = 0; j < 8; j++) {
            int hh = q * 8 + j;
            float hv = hn[hh * 40 + w];
            so += W_out[hh]  * hv;
            si += W_init[hh] * hv;
        }
        part[q * 32 + w]       = so;
        part[256 + q * 32 + w] = si;
    }
    __syncthreads();
    if (tid < TN) {
        int w = tid;
        float so = 0.f, si = 0.f;
        #pragma unroll
        for (int q = 0; q < 8; q++) {
            so += part[q * 32 + w];
            si += part[256 + q * 32 + w];
        }
        stcs(&out_imps[(b * NV + w0 + w) * NT + t], so + b_out[0]);
        if (t < NT - 1) {
            float d = si + b_init[0];
            int xi = (b * NV + w0 + w) * NT + (t + 1);
            g_xh[b][w0 + w] = (smk[w] != 0.f) ? sx[w] : d;
            stcs(&out_preds[xi], d);
        }
    }
}

// ---------------------------------------------------------------------------
extern "C" void kernel_launch(void* const* d_in, const int* in_sizes, int n_in,
                              void* d_out, int out_size) {
    const float* x          = (const float*)d_in[0];
    const unsigned char* mk = (const unsigned char*)d_in[1];
    const float* graph      = (const float*)d_in[2];
    const float* ind_graph  = (const float*)d_in[3];
    const float* h0         = (const float*)d_in[4];
    const float* W_init     = (const float*)d_in[5];
    const float* b_init     = (const float*)d_in[6];
    const float* W_out      = (const float*)d_in[7];
    const float* b_out      = (const float*)d_in[8];
    const float* W_ih       = (const float*)d_in[9];
    const float* W_hh       = (const float*)d_in[10];
    const float* b_ih       = (const float*)d_in[11];
    const float* b_hh       = (const float*)d_in[12];

    float* out_imps  = (float*)d_out;
    float* out_preds = out_imps + BSZ * NV * NT;
    float* out_reprs = out_preds + BSZ * NV * NT;

    cudaFuncSetAttribute(step_tc_kernel, cudaFuncAttributeMaxDynamicSharedMemorySize,
                         SMEM_TOTAL);

    detect_mask_kernel<<<1, 256>>>((const unsigned int*)mk);
    setup_kernel<<<NV * NV / 256, 256>>>(graph, W_hh, h0);
    prep_kernel<<<dim3(4, BSZ), 256>>>(x, mk, h0, W_init, b_init, out_preds);
    for (int t = 0; t < NT; t++) {
        step_tc_kernel<<<dim3(32, BSZ), 256, SMEM_TOTAL>>>(
            t, t & 1, x, mk, ind_graph,
            W_init, b_init, W_out, b_out, W_ih, b_ih, b_hh,
            out_imps, out_preds, out_reprs);
    }
}

// round 10
// speedup vs baseline: 1.1589x; 1.1589x over previous
#include <cuda_runtime.h>
#include <cuda_bf16.h>
#include <mma.h>
#include <cstdint>

using namespace nvcuda;

#define BSZ 8
#define HID 64
#define NV  1024
#define NT  64

// bf16 hi/lo split state [buf][(b*64+hid)*NV + v]
__device__ __nv_bfloat16 g_hh[2][BSZ * HID * NV];
__device__ __nv_bfloat16 g_hl[2][BSZ * HID * NV];
__device__ __nv_bfloat16 g_gh[NV * NV];       // graph hi  [w][v]
__device__ __nv_bfloat16 g_gl[NV * NV];       // graph lo
__device__ __nv_bfloat16 g_whh_h[192 * 64];   // W_hh hi [gate][hid]
__device__ __nv_bfloat16 g_whh_l[192 * 64];
__device__ float g_xh[BSZ][NV];
__device__ int   g_mask_mode;                 // 0=byte, 1=int32, 2=float32

// smem byte offsets — 3-stage GEMM buffers, post-GEMM regions alias them
#define ST_AH(s) ((s) * 9216)                 // [64m][72] bf16 hi
#define ST_AL(s) (27648 + (s) * 9216)
#define ST_BH(s) (55296 + (s) * 9216)         // [64n][72] bf16 hi
#define ST_BL(s) (82944 + (s) * 9216)
#define OFF_HD   0          // f32 [64][72]  (aliases AH s0-s1)
#define OFF_HDH  18432      // bf16 [64][72] (aliases AH s2)
#define OFF_HDL  27648      // bf16 [64][72] (aliases AL s0)
#define OFF_GD   36864      // f32 [192][72] (aliases AL s1..BL s0)
#define OFF_HN   92160      // f32 [64][72]  (aliases BL s1-s2)
#define OFF_XG   110592     // f32 [64]
#define OFF_PART 110848     // f32 [512]
#define OFF_SX   112896     // f32 [64]
#define OFF_SMK  113152     // f32 [64]
#define OFF_WH   113408     // bf16 [192][64]
#define OFF_WL   137984     // bf16 [192][64]
#define SMEM_TOTAL 162560

// ---------------------------------------------------------------------------
__device__ __forceinline__ void cp_async16(uint32_t s, const void* g) {
    asm volatile("cp.async.ca.shared.global [%0], [%1], 16;" :: "r"(s), "l"(g));
}
__device__ __forceinline__ void cp_commit() { asm volatile("cp.async.commit_group;"); }
__device__ __forceinline__ void cp_wait0()  { asm volatile("cp.async.wait_group 0;"); }
__device__ __forceinline__ void cp_wait1()  { asm volatile("cp.async.wait_group 1;"); }
__device__ __forceinline__ void cp_wait2()  { asm volatile("cp.async.wait_group 2;"); }
__device__ __forceinline__ void stcs(float* p, float v) {
    asm volatile("st.global.cs.f32 [%0], %1;" :: "l"(p), "f"(v));
}
__device__ __forceinline__ float tanh_fast(float x) {
    float y;
    asm("tanh.approx.f32 %0, %1;" : "=f"(y) : "f"(x));
    return y;
}

// ---------------------------------------------------------------------------
__global__ void detect_mask_kernel(const unsigned int* __restrict__ m) {
    __shared__ int viol_i, viol_f;
    if (threadIdx.x == 0) { viol_i = 0; viol_f = 0; }
    __syncthreads();
    int li = 0, lf = 0;
    const int nwords = (BSZ * NV * NT) / 4;
    for (int i = threadIdx.x; i < nwords; i += blockDim.x) {
        unsigned int w = m[i];
        if (w > 1u) li = 1;
        if (w != 0u && w != 0x3F800000u) lf = 1;
    }
    if (li) atomicOr(&viol_i, 1);
    if (lf) atomicOr(&viol_f, 1);
    __syncthreads();
    if (threadIdx.x == 0)
        g_mask_mode = (!viol_f) ? 2 : ((!viol_i) ? 1 : 0);
}

// Merged one-time setup: graph split, W_hh split, h0 init.
__global__ void setup_kernel(const float* __restrict__ graph,
                             const float* __restrict__ W_hh,
                             const float* __restrict__ h0) {
    int i = blockIdx.x * blockDim.x + threadIdx.x;
    {
        float v = graph[i];
        __nv_bfloat16 hi = __float2bfloat16(v);
        g_gh[i] = hi;
        g_gl[i] = __float2bfloat16(v - __bfloat162float(hi));
    }
    if (i < 192 * 64) {
        float v = W_hh[i];
        __nv_bfloat16 hi = __float2bfloat16(v);
        g_whh_h[i] = hi;
        g_whh_l[i] = __float2bfloat16(v - __bfloat162float(hi));
    }
    if (i < BSZ * HID * NV) {
        int v  = i & (NV - 1);
        int hh = (i >> 10) & 63;
        float val = h0[hh * NV + v];
        __nv_bfloat16 hi = __float2bfloat16(val);
        g_hh[0][i] = hi;
        g_hl[0][i] = __float2bfloat16(val - __bfloat162float(hi));
    }
}

// t=0 prep from h0 directly. Grid (4, 8), 256 threads.
__global__ void prep_kernel(
    const float* __restrict__ x, const unsigned char* __restrict__ mask_raw,
    const float* __restrict__ h0,
    const float* __restrict__ W_init, const float* __restrict__ b_init,
    float* __restrict__ out_preds)
{
    int b = blockIdx.y;
    int v = blockIdx.x * 256 + threadIdx.x;
    float d = 0.f;
    #pragma unroll 16
    for (int hh = 0; hh < HID; hh++) d += W_init[hh] * h0[hh * NV + v];
    d += b_init[0];
    int xi = (b * NV + v) * NT + 0;
    int mode = g_mask_mode;
    bool m;
    if (mode == 0)      m = mask_raw[xi] != 0;
    else if (mode == 1) m = ((const int*)mask_raw)[xi] != 0;
    else                m = ((const float*)mask_raw)[xi] != 0.f;
    g_xh[b][v] = m ? x[xi] : d;
    out_preds[xi] = d;
}

// ---------------------------------------------------------------------------
// Step kernel: grid (16 w-tiles, 8 batches) = 128 CTAs, 256 threads (8 warps).
// 3-stage cp.async pipeline, ONE barrier per k-iteration.
// ---------------------------------------------------------------------------
__global__ void __launch_bounds__(256) step_tc_kernel(int t, int cur,
    const float* __restrict__ x, const unsigned char* __restrict__ mask_raw,
    const float* __restrict__ ind_graph,
    const float* __restrict__ W_init, const float* __restrict__ b_init,
    const float* __restrict__ W_out,  const float* __restrict__ b_out,
    const float* __restrict__ W_ih,
    const float* __restrict__ b_ih,   const float* __restrict__ b_hh,
    float* __restrict__ out_imps, float* __restrict__ out_preds,
    float* __restrict__ out_reprs)
{
    extern __shared__ __align__(32) char smem[];
    const uint32_t sbase = (uint32_t)__cvta_generic_to_shared(smem);

    const int tid  = threadIdx.x;
    const int wid  = tid >> 5;
    const int wt   = blockIdx.x;
    const int b    = blockIdx.y;          // batch == m-tile
    const int w0   = wt * 64;
    const int m0   = b * 64;
    const int nxt  = cur ^ 1;

    float* hd   = (float*)(smem + OFF_HD);
    __nv_bfloat16* hdh = (__nv_bfloat16*)(smem + OFF_HDH);
    __nv_bfloat16* hdl = (__nv_bfloat16*)(smem + OFF_HDL);
    float* gd   = (float*)(smem + OFF_GD);
    float* hn   = (float*)(smem + OFF_HN);
    float* xg   = (float*)(smem + OFF_XG);
    float* part = (float*)(smem + OFF_PART);
    float* sx   = (float*)(smem + OFF_SX);
    float* smk  = (float*)(smem + OFF_SMK);
    __nv_bfloat16* swh = (__nv_bfloat16*)(smem + OFF_WH);
    __nv_bfloat16* swl = (__nv_bfloat16*)(smem + OFF_WL);

    // fill(kt): cp.async A/B hi/lo bf16 64x64 tiles into stage kt%3, ld=72.
    auto fill = [&](int kt) {
        int s  = kt % 3;
        int v0 = kt * 64;
        const __nv_bfloat16* srcs[4] = {
            g_hh[cur] + (size_t)m0 * NV + v0,
            g_hl[cur] + (size_t)m0 * NV + v0,
            g_gh      + (size_t)w0 * NV + v0,
            g_gl      + (size_t)w0 * NV + v0 };
        const uint32_t dsts[4] = {
            sbase + ST_AH(s), sbase + ST_AL(s),
            sbase + ST_BH(s), sbase + ST_BL(s) };
        #pragma unroll
        for (int i = 0; i < 8; i++) {
            const int mat = i >> 1;
            int cc = (i & 1) * 256 + tid;       // 0..511
            int row = cc >> 3, kc = cc & 7;
            cp_async16(dsts[mat] + row * 144 + kc * 16,
                       srcs[mat] + row * NV + kc * 8);
        }
        cp_commit();
    };

    // prologue: tiles 0,1 in their own groups, then W_hh (own group, needed late)
    fill(0);
    fill(1);
    {
        #pragma unroll
        for (int r = 0; r < 6; r++) {
            int c = r * 256 + tid;              // 1536 chunks x 16B
            cp_async16(sbase + OFF_WH + c * 16, (const char*)g_whh_h + c * 16);
            cp_async16(sbase + OFF_WL + c * 16, (const char*)g_whh_l + c * 16);
        }
        cp_commit();
    }

    // ---- prefetch x/mask for t+1 (overlapped) ----
    if (tid >= 192 && t < NT - 1) {
        int w = tid - 192;
        int xi = (b * NV + w0 + w) * NT + (t + 1);
        int mode = g_mask_mode;
        bool m;
        if (mode == 0)      m = mask_raw[xi] != 0;
        else if (mode == 1) m = ((const int*)mask_raw)[xi] != 0;
        else                m = ((const float*)mask_raw)[xi] != 0.f;
        smk[w] = m ? 1.f : 0.f;
        sx[w]  = x[xi];
    }

    // ---- x_g[w] = sum_v g_xh[b][v] * ind_graph[w0+w][v] (overlaps prologue) ----
    {
        int w = tid & 63, q = tid >> 6;
        const float4* ig = (const float4*)&ind_graph[(w0 + w) * NV + q * 256];
        const float4* xh = (const float4*)&g_xh[b][q * 256];
        float s = 0.f;
        #pragma unroll 16
        for (int j = 0; j < 64; j++) {
            float4 a = ig[j], c = xh[j];
            s += a.x * c.x + a.y * c.y + a.z * c.z + a.w * c.w;
        }
        part[q * 64 + w] = s;
    }
    __syncthreads();
    if (tid < 64)
        xg[tid] = part[tid] + part[64 + tid] + part[128 + tid] + part[192 + tid];

    // ---- GEMM: warp (wm = wid&3 -> m-tile, wn = wid>>2 -> 2 n-tiles) ----
    wmma::fragment<wmma::accumulator, 16, 16, 16, float> acc[2];
    wmma::fill_fragment(acc[0], 0.f);
    wmma::fill_fragment(acc[1], 0.f);
    const int wm = wid & 3, wn = wid >> 2;

    for (int kt = 0; kt < 16; kt++) {
        // wait for tile kt: groups retire in order (t0,t1,W,t2,t3,...)
        if (kt < 2)       cp_wait2();
        else if (kt < 15) cp_wait1();
        else              cp_wait0();
        __syncthreads();                 // stage kt%3 visible; stage (kt+2)%3 free
        if (kt < 14) fill(kt + 2);
        const int s = kt % 3;
        const __nv_bfloat16* Ah = (const __nv_bfloat16*)(smem + ST_AH(s));
        const __nv_bfloat16* Al = (const __nv_bfloat16*)(smem + ST_AL(s));
        const __nv_bfloat16* Bh = (const __nv_bfloat16*)(smem + ST_BH(s));
        const __nv_bfloat16* Bl = (const __nv_bfloat16*)(smem + ST_BL(s));
        #pragma unroll
        for (int ks = 0; ks < 4; ks++) {
            wmma::fragment<wmma::matrix_a, 16, 16, 16, __nv_bfloat16, wmma::row_major> fah, fal;
            wmma::load_matrix_sync(fah, Ah + wm * 16 * 72 + ks * 16, 72);
            wmma::load_matrix_sync(fal, Al + wm * 16 * 72 + ks * 16, 72);
            #pragma unroll
            for (int ni = 0; ni < 2; ni++) {
                wmma::fragment<wmma::matrix_b, 16, 16, 16, __nv_bfloat16, wmma::col_major> fbh, fbl;
                int boff = (wn * 2 + ni) * 16 * 72 + ks * 16;
                wmma::load_matrix_sync(fbh, Bh + boff, 72);
                wmma::load_matrix_sync(fbl, Bl + boff, 72);
                wmma::mma_sync(acc[ni], fah, fbh, acc[ni]);
                wmma::mma_sync(acc[ni], fah, fbl, acc[ni]);
                wmma::mma_sync(acc[ni], fal, fbh, acc[ni]);
            }
        }
    }
    __syncthreads();   // all MMAs/LDSM done before aliasing stage buffers

    // ---- store h_diff (f32) into smem [64][72] ----
    wmma::store_matrix_sync(hd + wm * 16 * 72 + (wn * 2 + 0) * 16, acc[0], 72, wmma::mem_row_major);
    wmma::store_matrix_sync(hd + wm * 16 * 72 + (wn * 2 + 1) * 16, acc[1], 72, wmma::mem_row_major);
    __syncthreads();

    // ---- split h_diff -> bf16 hi/lo for the gate GEMM ----
    #pragma unroll
    for (int i = 0; i < 16; i++) {
        int idx = tid + i * 256;               // 4096
        int row = idx >> 6, col = idx & 63;
        float v = hd[row * 72 + col];
        __nv_bfloat16 hi = __float2bfloat16(v);
        hdh[row * 72 + col] = hi;
        hdl[row * 72 + col] = __float2bfloat16(v - __bfloat162float(hi));
    }
    __syncthreads();

    // ---- gates GEMM: gd[192 x 64] = W_hh · h_diff (W from smem) ----
    {
        const int gm = wid >> 1, gn = wid & 1;   // 3 m-tiles, 2 n-tiles per warp
        wmma::fragment<wmma::accumulator, 16, 16, 16, float> gacc[3][2];
        #pragma unroll
        for (int mi = 0; mi < 3; mi++)
            #pragma unroll
            for (int ni = 0; ni < 2; ni++) wmma::fill_fragment(gacc[mi][ni], 0.f);
        #pragma unroll
        for (int ks = 0; ks < 4; ks++) {
            wmma::fragment<wmma::matrix_b, 16, 16, 16, __nv_bfloat16, wmma::row_major> gbh[2], gbl[2];
            #pragma unroll
            for (int ni = 0; ni < 2; ni++) {
                int boff = ks * 16 * 72 + (gn * 2 + ni) * 16;
                wmma::load_matrix_sync(gbh[ni], hdh + boff, 72);
                wmma::load_matrix_sync(gbl[ni], hdl + boff, 72);
            }
            #pragma unroll
            for (int mi = 0; mi < 3; mi++) {
                wmma::fragment<wmma::matrix_a, 16, 16, 16, __nv_bfloat16, wmma::row_major> fah, fal;
                int aoff = (gm * 3 + mi) * 16 * 64 + ks * 16;
                wmma::load_matrix_sync(fah, swh + aoff, 64);
                wmma::load_matrix_sync(fal, swl + aoff, 64);
                #pragma unroll
                for (int ni = 0; ni < 2; ni++) {
                    wmma::mma_sync(gacc[mi][ni], fah, gbh[ni], gacc[mi][ni]);
                    wmma::mma_sync(gacc[mi][ni], fah, gbl[ni], gacc[mi][ni]);
                    wmma::mma_sync(gacc[mi][ni], fal, gbh[ni], gacc[mi][ni]);
                }
            }
        }
        #pragma unroll
        for (int mi = 0; mi < 3; mi++)
            #pragma unroll
            for (int ni = 0; ni < 2; ni++)
                wmma::store_matrix_sync(gd + (gm * 3 + mi) * 16 * 72 + (gn * 2 + ni) * 16,
                                        gacc[mi][ni], 72, wmma::mem_row_major);
    }
    __syncthreads();

    // ---- nonlinearity + state update: thread = (hh, wq), 16 nodes ----
    {
        const int hh = tid >> 2;
        const int wq = tid & 3;
        float wih_r = W_ih[hh],  wih_z = W_ih[64 + hh],  wih_n = W_ih[128 + hh];
        float bi_r  = b_ih[hh] + b_hh[hh];
        float bi_z  = b_ih[64 + hh] + b_hh[64 + hh];
        float bi_n  = b_ih[128 + hh];
        float bh_n  = b_hh[128 + hh];
        #pragma unroll
        for (int k = 0; k < 16; k++) {
            int w = wq + 4 * k;
            float ar = gd[hh * 72 + w];
            float az = gd[(64 + hh) * 72 + w];
            float an = gd[(128 + hh) * 72 + w];
            float xgv = xg[w];
            float r = 0.5f + 0.5f * tanh_fast(0.5f * (ar + wih_r * xgv + bi_r));
            float z = 0.5f + 0.5f * tanh_fast(0.5f * (az + wih_z * xgv + bi_z));
            float n = tanh_fast(wih_n * xgv + bi_n + r * (an + bh_n));
            float hd_self = hd[hh * 72 + w];
            float hnew = (1.f - z) * n + z * hd_self;
            size_t si = (size_t)(m0 + hh) * NV + w0 + w;
            __nv_bfloat16 hi = __float2bfloat16(hnew);
            g_hh[nxt][si] = hi;
            g_hl[nxt][si] = __float2bfloat16(hnew - __bfloat162float(hi));
            stcs(&out_reprs[((b * HID + hh) * NV + (w0 + w)) * NT + t], hnew);
            hn[hh * 72 + w] = hnew;
        }
    }
    __syncthreads();

    // ---- fused epilogue: imps(t), preds(t+1), g_xh(t+1) ----
    {
        int w = tid & 63, q = tid >> 6;
        float so = 0.f, si = 0.f;
        #pragma unroll
        for (int j = 0; j < 16; j++) {
            int hh = q * 16 + j;
            float hv = hn[hh * 72 + w];
            so += W_out[hh]  * hv;
            si += W_init[hh] * hv;
        }
        part[q * 64 + w]       = so;
        part[256 + q * 64 + w] = si;
    }
    __syncthreads();
    if (tid < 64) {
        int w = tid;
        float so = part[w] + part[64 + w] + part[128 + w] + part[192 + w];
        stcs(&out_imps[(b * NV + w0 + w) * NT + t], so + b_out[0]);
        if (t < NT - 1) {
            float si = part[256 + w] + part[320 + w] + part[384 + w] + part[448 + w];
            float d = si + b_init[0];
            int xi = (b * NV + w0 + w) * NT + (t + 1);
            g_xh[b][w0 + w] = (smk[w] != 0.f) ? sx[w] : d;
            stcs(&out_preds[xi], d);
        }
    }
}

// ---------------------------------------------------------------------------
extern "C" void kernel_launch(void* const* d_in, const int* in_sizes, int n_in,
                              void* d_out, int out_size) {
    const float* x          = (const float*)d_in[0];
    const unsigned char* mk = (const unsigned char*)d_in[1];
    const float* graph      = (const float*)d_in[2];
    const float* ind_graph  = (const float*)d_in[3];
    const float* h0         = (const float*)d_in[4];
    const float* W_init     = (const float*)d_in[5];
    const float* b_init     = (const float*)d_in[6];
    const float* W_out      = (const float*)d_in[7];
    const float* b_out      = (const float*)d_in[8];
    const float* W_ih       = (const float*)d_in[9];
    const float* W_hh       = (const float*)d_in[10];
    const float* b_ih       = (const float*)d_in[11];
    const float* b_hh       = (const float*)d_in[12];

    float* out_imps  = (float*)d_out;
    float* out_preds = out_imps + BSZ * NV * NT;
    float* out_reprs = out_preds + BSZ * NV * NT;

    cudaFuncSetAttribute(step_tc_kernel, cudaFuncAttributeMaxDynamicSharedMemorySize,
                         SMEM_TOTAL);

    detect_mask_kernel<<<1, 256>>>((const unsigned int*)mk);
    setup_kernel<<<NV * NV / 256, 256>>>(graph, W_hh, h0);
    prep_kernel<<<dim3(4, BSZ), 256>>>(x, mk, h0, W_init, b_init, out_preds);
    for (int t = 0; t < NT; t++) {
        step_tc_kernel<<<dim3(16, BSZ), 256, SMEM_TOTAL>>>(
            t, t & 1, x, mk, ind_graph,
            W_init, b_init, W_out, b_out, W_ih, b_ih, b_hh,
            out_imps, out_preds, out_reprs);
    }
}

// round 11
// speedup vs baseline: 1.2530x; 1.0812x over previous
#include <cuda_runtime.h>
#include <cuda_bf16.h>
#include <mma.h>
#include <cstdint>

using namespace nvcuda;

#define BSZ 8
#define HID 64
#define NV  1024
#define NT  64
#define BHW (BSZ * HID * NV)

// bf16 hi/lo split state [buf][(b*64+hid)*NV + v]
__device__ __nv_bfloat16 g_hh[2][BHW];
__device__ __nv_bfloat16 g_hl[2][BHW];
__device__ __nv_bfloat16 g_gh[NV * NV];       // graph hi  [w][v]
__device__ __nv_bfloat16 g_gl[NV * NV];       // graph lo
__device__ __nv_bfloat16 g_whh_h[192 * 64];   // W_hh hi [gate][hid]
__device__ __nv_bfloat16 g_whh_l[192 * 64];
__device__ float g_xh[BSZ][NV];
__device__ float g_reprs[(size_t)NT * BHW];   // step-major staging for reprs
__device__ int   g_mask_mode;                 // 0=byte, 1=int32, 2=float32

// smem byte offsets (buffers aliased after GEMM)
#define OFF_AH(b) ((b) * 9216)
#define OFF_AL(b) (18432 + (b) * 9216)
#define OFF_BH(b) (36864 + (b) * 9216)
#define OFF_BL(b) (55296 + (b) * 9216)
#define OFF_HD   0          // f32 [64][72]  (aliases AH)
#define OFF_HDH  18432      // bf16 [64][72] (aliases AL)
#define OFF_HDL  27648
#define OFF_GD   73728      // f32 [192][72]
#define OFF_HN   129024     // f32 [64][72]
#define OFF_XG   147456     // f32 [64]
#define OFF_PART 147712     // f32 [512]
#define OFF_SX   149760     // f32 [64]  x(t+1)
#define OFF_SMK  150016     // f32 [64]  mask(t+1) as 0/1
#define OFF_WH   150272     // bf16 [192][64] W_hh hi
#define OFF_WL   174848     // bf16 [192][64] W_hh lo
#define OFF_GW   199424     // f32 7 x [64]: Wr,Wz,Wn,Br,Bz,Bn,Bhn
#define SMEM_TOTAL 201216

// ---------------------------------------------------------------------------
__device__ __forceinline__ void cp_async16(uint32_t s, const void* g) {
    asm volatile("cp.async.ca.shared.global [%0], [%1], 16;" :: "r"(s), "l"(g));
}
__device__ __forceinline__ void cp_commit() { asm volatile("cp.async.commit_group;"); }
__device__ __forceinline__ void cp_wait0()  { asm volatile("cp.async.wait_group 0;"); }
__device__ __forceinline__ void cp_wait1()  { asm volatile("cp.async.wait_group 1;"); }
__device__ __forceinline__ void cp_wait2()  { asm volatile("cp.async.wait_group 2;"); }
__device__ __forceinline__ void stcs(float* p, float v) {
    asm volatile("st.global.cs.f32 [%0], %1;" :: "l"(p), "f"(v));
}
__device__ __forceinline__ float tanh_fast(float x) {
    float y;
    asm("tanh.approx.f32 %0, %1;" : "=f"(y) : "f"(x));
    return y;
}

// ---------------------------------------------------------------------------
__global__ void detect_mask_kernel(const unsigned int* __restrict__ m) {
    __shared__ int viol_i, viol_f;
    if (threadIdx.x == 0) { viol_i = 0; viol_f = 0; }
    __syncthreads();
    int li = 0, lf = 0;
    const int nwords = (BSZ * NV * NT) / 4;
    for (int i = threadIdx.x; i < nwords; i += blockDim.x) {
        unsigned int w = m[i];
        if (w > 1u) li = 1;
        if (w != 0u && w != 0x3F800000u) lf = 1;
    }
    if (li) atomicOr(&viol_i, 1);
    if (lf) atomicOr(&viol_f, 1);
    __syncthreads();
    if (threadIdx.x == 0)
        g_mask_mode = (!viol_f) ? 2 : ((!viol_i) ? 1 : 0);
}

// Merged one-time setup: graph split, W_hh split, h0 init.
__global__ void setup_kernel(const float* __restrict__ graph,
                             const float* __restrict__ W_hh,
                             const float* __restrict__ h0) {
    int i = blockIdx.x * blockDim.x + threadIdx.x;
    {
        float v = graph[i];
        __nv_bfloat16 hi = __float2bfloat16(v);
        g_gh[i] = hi;
        g_gl[i] = __float2bfloat16(v - __bfloat162float(hi));
    }
    if (i < 192 * 64) {
        float v = W_hh[i];
        __nv_bfloat16 hi = __float2bfloat16(v);
        g_whh_h[i] = hi;
        g_whh_l[i] = __float2bfloat16(v - __bfloat162float(hi));
    }
    if (i < BHW) {
        int v  = i & (NV - 1);
        int hh = (i >> 10) & 63;
        float val = h0[hh * NV + v];
        __nv_bfloat16 hi = __float2bfloat16(val);
        g_hh[0][i] = hi;
        g_hl[0][i] = __float2bfloat16(val - __bfloat162float(hi));
    }
}

// t=0 prep from h0 directly. Grid (4, 8), 256 threads.
__global__ void prep_kernel(
    const float* __restrict__ x, const unsigned char* __restrict__ mask_raw,
    const float* __restrict__ h0,
    const float* __restrict__ W_init, const float* __restrict__ b_init,
    float* __restrict__ out_preds)
{
    int b = blockIdx.y;
    int v = blockIdx.x * 256 + threadIdx.x;
    float d = 0.f;
    #pragma unroll 16
    for (int hh = 0; hh < HID; hh++) d += W_init[hh] * h0[hh * NV + v];
    d += b_init[0];
    int xi = (b * NV + v) * NT + 0;
    int mode = g_mask_mode;
    bool m;
    if (mode == 0)      m = mask_raw[xi] != 0;
    else if (mode == 1) m = ((const int*)mask_raw)[xi] != 0;
    else                m = ((const float*)mask_raw)[xi] != 0.f;
    g_xh[b][v] = m ? x[xi] : d;
    out_preds[xi] = d;
}

// Final transpose: scratch [t][bhw] -> out_reprs [bhw][t]. 8192 blocks, 256 thr.
__global__ void __launch_bounds__(256) transpose_reprs_kernel(float* __restrict__ out) {
    __shared__ float sm[64][65];
    const int bhw0 = blockIdx.x * 64;
    const int c  = threadIdx.x & 63;
    const int r4 = threadIdx.x >> 6;
    #pragma unroll
    for (int i = 0; i < 16; i++) {
        int tt = r4 + 4 * i;
        sm[tt][c] = g_reprs[(size_t)tt * BHW + bhw0 + c];
    }
    __syncthreads();
    #pragma unroll
    for (int i = 0; i < 16; i++) {
        int row = r4 + 4 * i;
        out[(size_t)(bhw0 + row) * NT + c] = sm[c][row];
    }
}

// ---------------------------------------------------------------------------
// Step kernel: grid (16 w-tiles, 8 batches), 256 threads (8 warps).
// ---------------------------------------------------------------------------
__global__ void __launch_bounds__(256) step_tc_kernel(int t, int cur,
    const float* __restrict__ x, const unsigned char* __restrict__ mask_raw,
    const float* __restrict__ ind_graph,
    const float* __restrict__ W_init, const float* __restrict__ b_init,
    const float* __restrict__ W_out,  const float* __restrict__ b_out,
    const float* __restrict__ W_ih,
    const float* __restrict__ b_ih,   const float* __restrict__ b_hh,
    float* __restrict__ out_imps, float* __restrict__ out_preds)
{
    extern __shared__ __align__(32) char smem[];
    const uint32_t sbase = (uint32_t)__cvta_generic_to_shared(smem);

    const int tid  = threadIdx.x;
    const int wid  = tid >> 5;
    const int wt   = blockIdx.x;
    const int b    = blockIdx.y;          // batch == m-tile
    const int w0   = wt * 64;
    const int m0   = b * 64;
    const int nxt  = cur ^ 1;

    float* hd   = (float*)(smem + OFF_HD);
    __nv_bfloat16* hdh = (__nv_bfloat16*)(smem + OFF_HDH);
    __nv_bfloat16* hdl = (__nv_bfloat16*)(smem + OFF_HDL);
    float* gd   = (float*)(smem + OFF_GD);
    float* hn   = (float*)(smem + OFF_HN);
    float* xg   = (float*)(smem + OFF_XG);
    float* part = (float*)(smem + OFF_PART);
    float* sx   = (float*)(smem + OFF_SX);
    float* smk  = (float*)(smem + OFF_SMK);
    __nv_bfloat16* swh = (__nv_bfloat16*)(smem + OFF_WH);
    __nv_bfloat16* swl = (__nv_bfloat16*)(smem + OFF_WL);
    float* gw   = (float*)(smem + OFF_GW);   // 7 x [64]

    // fill(kt): cp.async 4 bf16 tiles (Ah, Al, Bh, Bl), 64 rows x 64 cols, ld=72.
    auto fill = [&](int kt) {
        int buf = kt & 1;
        int v0  = kt * 64;
        const __nv_bfloat16* srcs[4] = {
            g_hh[cur] + (size_t)m0 * NV + v0,
            g_hl[cur] + (size_t)m0 * NV + v0,
            g_gh      + (size_t)w0 * NV + v0,
            g_gl      + (size_t)w0 * NV + v0 };
        const uint32_t dsts[4] = {
            sbase + OFF_AH(buf), sbase + OFF_AL(buf),
            sbase + OFF_BH(buf), sbase + OFF_BL(buf) };
        #pragma unroll
        for (int i = 0; i < 8; i++) {
            const int mat = i >> 1;
            int cc = (i & 1) * 256 + tid;       // 0..511
            int row = cc >> 3, kc = cc & 7;
            cp_async16(dsts[mat] + row * 144 + kc * 16,
                       srcs[mat] + row * NV + kc * 8);
        }
    };

    // prologue: tile 0 (own group), then W_hh copy (own group, needed later)
    fill(0);
    cp_commit();
    {
        #pragma unroll
        for (int r = 0; r < 6; r++) {
            int c = r * 256 + tid;              // 1536 chunks x 16B
            cp_async16(sbase + OFF_WH + c * 16, (const char*)g_whh_h + c * 16);
            cp_async16(sbase + OFF_WL + c * 16, (const char*)g_whh_l + c * 16);
        }
        cp_commit();
    }

    // ---- stage gate weights/biases (per-hh) into smem ----
    if (tid < 64) {
        gw[tid]       = W_ih[tid];                        // Wr
        gw[64 + tid]  = W_ih[64 + tid];                   // Wz
        gw[128 + tid] = W_ih[128 + tid];                  // Wn
        gw[192 + tid] = b_ih[tid] + b_hh[tid];            // Br
        gw[256 + tid] = b_ih[64 + tid] + b_hh[64 + tid];  // Bz
        gw[320 + tid] = b_ih[128 + tid];                  // Bn
        gw[384 + tid] = b_hh[128 + tid];                  // Bhn
    }

    // ---- prefetch x/mask for t+1 (overlapped) ----
    if (tid >= 192 && t < NT - 1) {
        int w = tid - 192;
        int xi = (b * NV + w0 + w) * NT + (t + 1);
        int mode = g_mask_mode;
        bool m;
        if (mode == 0)      m = mask_raw[xi] != 0;
        else if (mode == 1) m = ((const int*)mask_raw)[xi] != 0;
        else                m = ((const float*)mask_raw)[xi] != 0.f;
        smk[w] = m ? 1.f : 0.f;
        sx[w]  = x[xi];
    }

    // ---- x_g[w] = sum_v g_xh[b][v] * ind_graph[w0+w][v] (overlaps prologue) ----
    {
        int w = tid & 63, q = tid >> 6;
        const float4* ig = (const float4*)&ind_graph[(w0 + w) * NV + q * 256];
        const float4* xh = (const float4*)&g_xh[b][q * 256];
        float s = 0.f;
        #pragma unroll 16
        for (int j = 0; j < 64; j++) {
            float4 a = ig[j], c = xh[j];
            s += a.x * c.x + a.y * c.y + a.z * c.z + a.w * c.w;
        }
        part[q * 64 + w] = s;
    }
    __syncthreads();
    if (tid < 64)
        xg[tid] = part[tid] + part[64 + tid] + part[128 + tid] + part[192 + tid];

    // ---- GEMM: warp (wm = wid&3 -> m-tile, wn = wid>>2 -> 2 n-tiles) ----
    wmma::fragment<wmma::accumulator, 16, 16, 16, float> acc[2];
    wmma::fill_fragment(acc[0], 0.f);
    wmma::fill_fragment(acc[1], 0.f);
    const int wm = wid & 3, wn = wid >> 2;

    for (int kt = 0; kt < 16; kt++) {
        if (kt < 15) {
            fill(kt + 1); cp_commit();
            if (kt == 0) cp_wait2();   // pending: W, t1 -> t0 done
            else         cp_wait1();   // pending: t(kt+1) -> t(kt) done
        } else {
            cp_wait0();
        }
        __syncthreads();                         // buffer kt ready
        const int buf = kt & 1;
        const __nv_bfloat16* Ah = (const __nv_bfloat16*)(smem + OFF_AH(buf));
        const __nv_bfloat16* Al = (const __nv_bfloat16*)(smem + OFF_AL(buf));
        const __nv_bfloat16* Bh = (const __nv_bfloat16*)(smem + OFF_BH(buf));
        const __nv_bfloat16* Bl = (const __nv_bfloat16*)(smem + OFF_BL(buf));
        #pragma unroll
        for (int ks = 0; ks < 4; ks++) {
            wmma::fragment<wmma::matrix_a, 16, 16, 16, __nv_bfloat16, wmma::row_major> fah, fal;
            wmma::load_matrix_sync(fah, Ah + wm * 16 * 72 + ks * 16, 72);
            wmma::load_matrix_sync(fal, Al + wm * 16 * 72 + ks * 16, 72);
            #pragma unroll
            for (int ni = 0; ni < 2; ni++) {
                wmma::fragment<wmma::matrix_b, 16, 16, 16, __nv_bfloat16, wmma::col_major> fbh, fbl;
                int boff = (wn * 2 + ni) * 16 * 72 + ks * 16;
                wmma::load_matrix_sync(fbh, Bh + boff, 72);
                wmma::load_matrix_sync(fbl, Bl + boff, 72);
                wmma::mma_sync(acc[ni], fah, fbh, acc[ni]);
                wmma::mma_sync(acc[ni], fah, fbl, acc[ni]);
                wmma::mma_sync(acc[ni], fal, fbh, acc[ni]);
            }
        }
        __syncthreads();                         // all reads done before refill
    }

    // ---- store h_diff (f32) into smem [64][72] (aliases dead buffers) ----
    wmma::store_matrix_sync(hd + wm * 16 * 72 + (wn * 2 + 0) * 16, acc[0], 72, wmma::mem_row_major);
    wmma::store_matrix_sync(hd + wm * 16 * 72 + (wn * 2 + 1) * 16, acc[1], 72, wmma::mem_row_major);
    __syncthreads();

    // ---- split h_diff -> bf16 hi/lo for the gate GEMM ----
    #pragma unroll
    for (int i = 0; i < 16; i++) {
        int idx = tid + i * 256;               // 4096
        int row = idx >> 6, col = idx & 63;
        float v = hd[row * 72 + col];
        __nv_bfloat16 hi = __float2bfloat16(v);
        hdh[row * 72 + col] = hi;
        hdl[row * 72 + col] = __float2bfloat16(v - __bfloat162float(hi));
    }
    __syncthreads();

    // ---- gates GEMM: gd[192 x 64] = W_hh · h_diff (W from smem) ----
    {
        const int gm = wid >> 1, gn = wid & 1;   // 3 m-tiles, 2 n-tiles per warp
        wmma::fragment<wmma::accumulator, 16, 16, 16, float> gacc[3][2];
        #pragma unroll
        for (int mi = 0; mi < 3; mi++)
            #pragma unroll
            for (int ni = 0; ni < 2; ni++) wmma::fill_fragment(gacc[mi][ni], 0.f);
        #pragma unroll
        for (int ks = 0; ks < 4; ks++) {
            wmma::fragment<wmma::matrix_b, 16, 16, 16, __nv_bfloat16, wmma::row_major> gbh[2], gbl[2];
            #pragma unroll
            for (int ni = 0; ni < 2; ni++) {
                int boff = ks * 16 * 72 + (gn * 2 + ni) * 16;
                wmma::load_matrix_sync(gbh[ni], hdh + boff, 72);
                wmma::load_matrix_sync(gbl[ni], hdl + boff, 72);
            }
            #pragma unroll
            for (int mi = 0; mi < 3; mi++) {
                wmma::fragment<wmma::matrix_a, 16, 16, 16, __nv_bfloat16, wmma::row_major> fah, fal;
                int aoff = (gm * 3 + mi) * 16 * 64 + ks * 16;
                wmma::load_matrix_sync(fah, swh + aoff, 64);
                wmma::load_matrix_sync(fal, swl + aoff, 64);
                #pragma unroll
                for (int ni = 0; ni < 2; ni++) {
                    wmma::mma_sync(gacc[mi][ni], fah, gbh[ni], gacc[mi][ni]);
                    wmma::mma_sync(gacc[mi][ni], fah, gbl[ni], gacc[mi][ni]);
                    wmma::mma_sync(gacc[mi][ni], fal, gbh[ni], gacc[mi][ni]);
                }
            }
        }
        #pragma unroll
        for (int mi = 0; mi < 3; mi++)
            #pragma unroll
            for (int ni = 0; ni < 2; ni++)
                wmma::store_matrix_sync(gd + (gm * 3 + mi) * 16 * 72 + (gn * 2 + ni) * 16,
                                        gacc[mi][ni], 72, wmma::mem_row_major);
    }
    __syncthreads();

    // ---- nonlinearity + state update: thread = (q, w); warp = 32 contiguous w
    //      so all global stores are 64-128B contiguous lines ----
    {
        const int w = tid & 63;
        const int q = tid >> 6;
        float xgv = xg[w];
        float mskv = 0.f, xv = 0.f;
        if (t < NT - 1) { mskv = smk[w]; xv = sx[w]; }
        (void)mskv; (void)xv;
        #pragma unroll
        for (int k = 0; k < 16; k++) {
            int hh = q + 4 * k;
            float ar = gd[hh * 72 + w];
            float az = gd[(64 + hh) * 72 + w];
            float an = gd[(128 + hh) * 72 + w];
            float r = 0.5f + 0.5f * tanh_fast(0.5f * (ar + gw[hh] * xgv + gw[192 + hh]));
            float z = 0.5f + 0.5f * tanh_fast(0.5f * (az + gw[64 + hh] * xgv + gw[256 + hh]));
            float n = tanh_fast(gw[128 + hh] * xgv + gw[320 + hh] + r * (an + gw[384 + hh]));
            float hd_self = hd[hh * 72 + w];
            float hnew = (1.f - z) * n + z * hd_self;
            size_t si = (size_t)(m0 + hh) * NV + w0 + w;
            __nv_bfloat16 hi = __float2bfloat16(hnew);
            g_hh[nxt][si] = hi;
            g_hl[nxt][si] = __float2bfloat16(hnew - __bfloat162float(hi));
            g_reprs[(size_t)t * BHW + si] = hnew;     // coalesced 128B lines
            hn[hh * 72 + w] = hnew;
        }
    }
    __syncthreads();

    // ---- fused epilogue: imps(t), preds(t+1), g_xh(t+1) ----
    {
        int w = tid & 63, q = tid >> 6;
        float so = 0.f, si = 0.f;
        #pragma unroll
        for (int j = 0; j < 16; j++) {
            int hh = q * 16 + j;
            float hv = hn[hh * 72 + w];
            so += W_out[hh]  * hv;
            si += W_init[hh] * hv;
        }
        part[q * 64 + w]       = so;
        part[256 + q * 64 + w] = si;
    }
    __syncthreads();
    if (tid < 64) {
        int w = tid;
        float so = part[w] + part[64 + w] + part[128 + w] + part[192 + w];
        stcs(&out_imps[(b * NV + w0 + w) * NT + t], so + b_out[0]);
        if (t < NT - 1) {
            float si = part[256 + w] + part[320 + w] + part[384 + w] + part[448 + w];
            float d = si + b_init[0];
            int xi = (b * NV + w0 + w) * NT + (t + 1);
            g_xh[b][w0 + w] = (smk[w] != 0.f) ? sx[w] : d;
            stcs(&out_preds[xi], d);
        }
    }
}

// ---------------------------------------------------------------------------
extern "C" void kernel_launch(void* const* d_in, const int* in_sizes, int n_in,
                              void* d_out, int out_size) {
    const float* x          = (const float*)d_in[0];
    const unsigned char* mk = (const unsigned char*)d_in[1];
    const float* graph      = (const float*)d_in[2];
    const float* ind_graph  = (const float*)d_in[3];
    const float* h0         = (const float*)d_in[4];
    const float* W_init     = (const float*)d_in[5];
    const float* b_init     = (const float*)d_in[6];
    const float* W_out      = (const float*)d_in[7];
    const float* b_out      = (const float*)d_in[8];
    const float* W_ih       = (const float*)d_in[9];
    const float* W_hh       = (const float*)d_in[10];
    const float* b_ih       = (const float*)d_in[11];
    const float* b_hh       = (const float*)d_in[12];

    float* out_imps  = (float*)d_out;
    float* out_preds = out_imps + BSZ * NV * NT;
    float* out_reprs = out_preds + BSZ * NV * NT;

    cudaFuncSetAttribute(step_tc_kernel, cudaFuncAttributeMaxDynamicSharedMemorySize,
                         SMEM_TOTAL);

    detect_mask_kernel<<<1, 256>>>((const unsigned int*)mk);
    setup_kernel<<<NV * NV / 256, 256>>>(graph, W_hh, h0);
    prep_kernel<<<dim3(4, BSZ), 256>>>(x, mk, h0, W_init, b_init, out_preds);
    for (int t = 0; t < NT; t++) {
        step_tc_kernel<<<dim3(16, BSZ), 256, SMEM_TOTAL>>>(
            t, t & 1, x, mk, ind_graph,
            W_init, b_init, W_out, b_out, W_ih, b_ih, b_hh,
            out_imps, out_preds);
    }
    transpose_reprs_kernel<<<BHW / 64, 256>>>(out_reprs);
}

// round 14
// speedup vs baseline: 1.3849x; 1.1053x over previous
#include <cuda_runtime.h>
#include <cuda_bf16.h>
#include <mma.h>
#include <cstdint>

using namespace nvcuda;

#define BSZ 8
#define HID 64
#define NV  1024
#define NT  64
#define BHW (BSZ * HID * NV)

// bf16 hi/lo split state [buf][(b*64+hid)*NV + v]
__device__ __nv_bfloat16 g_hh[2][BHW];
__device__ __nv_bfloat16 g_hl[2][BHW];
__device__ __nv_bfloat16 g_gh[NV * NV];       // graph hi  [w][v]
__device__ __nv_bfloat16 g_gl[NV * NV];       // graph lo
__device__ __nv_bfloat16 g_whh_h[192 * 64];   // W_hh hi [gate][hid]
__device__ __nv_bfloat16 g_whh_l[192 * 64];
__device__ float g_xh[BSZ][NV];
__device__ float g_reprs[(size_t)NT * BHW];   // step-major staging for reprs
__device__ int   g_mask_mode;                 // 0=byte, 1=int32, 2=float32

// smem byte offsets. GEMM buffers: [64 rows][136 cols] bf16, k-chunk = 128.
#define LDT 136
#define TILE_B (64 * LDT * 2)                 // 17408
#define OFF_AH(b) ((b) * TILE_B)              // 0 .. 34816
#define OFF_AL(b) (34816 + (b) * TILE_B)      // 34816 .. 69632
#define OFF_BH(b) (69632 + (b) * TILE_B)      // 69632 .. 104448
#define OFF_BL(b) (104448 + (b) * TILE_B)     // 104448 .. 139264
// post-GEMM regions alias the dead GEMM buffers:
#define OFF_HD   0          // f32 [64][72]  = 18432
#define OFF_HDH  18432      // bf16 [64][72] = 9216
#define OFF_HDL  27648      // bf16 [64][72] = 9216
#define OFF_GD   36864      // f32 [192][72] = 55296 -> ends 92160
#define OFF_HN   92160      // f32 [64][72]  = 18432 -> ends 110592
// non-aliased tail:
#define OFF_XG   139264     // f32 [64]
#define OFF_PART 139520     // f32 [512]
#define OFF_SX   141568     // f32 [64]  x(t+1)
#define OFF_SMK  141824     // f32 [64]  mask(t+1) as 0/1
#define OFF_GW   142080     // f32 7 x [64]
#define SMEM_TOTAL 143872

// ---------------------------------------------------------------------------
__device__ __forceinline__ void cp_async16(uint32_t s, const void* g) {
    asm volatile("cp.async.ca.shared.global [%0], [%1], 16;" :: "r"(s), "l"(g));
}
__device__ __forceinline__ void cp_commit() { asm volatile("cp.async.commit_group;"); }
__device__ __forceinline__ void cp_wait0()  { asm volatile("cp.async.wait_group 0;"); }
__device__ __forceinline__ void cp_wait1()  { asm volatile("cp.async.wait_group 1;"); }
__device__ __forceinline__ void stcs(float* p, float v) {
    asm volatile("st.global.cs.f32 [%0], %1;" :: "l"(p), "f"(v));
}
__device__ __forceinline__ float tanh_fast(float x) {
    float y;
    asm("tanh.approx.f32 %0, %1;" : "=f"(y) : "f"(x));
    return y;
}

// ---------------------------------------------------------------------------
__global__ void detect_mask_kernel(const unsigned int* __restrict__ m) {
    __shared__ int viol_i, viol_f;
    if (threadIdx.x == 0) { viol_i = 0; viol_f = 0; }
    __syncthreads();
    int li = 0, lf = 0;
    const int nwords = (BSZ * NV * NT) / 4;
    for (int i = threadIdx.x; i < nwords; i += blockDim.x) {
        unsigned int w = m[i];
        if (w > 1u) li = 1;
        if (w != 0u && w != 0x3F800000u) lf = 1;
    }
    if (li) atomicOr(&viol_i, 1);
    if (lf) atomicOr(&viol_f, 1);
    __syncthreads();
    if (threadIdx.x == 0)
        g_mask_mode = (!viol_f) ? 2 : ((!viol_i) ? 1 : 0);
}

// Merged one-time setup: graph split, W_hh split, h0 init.
__global__ void setup_kernel(const float* __restrict__ graph,
                             const float* __restrict__ W_hh,
                             const float* __restrict__ h0) {
    int i = blockIdx.x * blockDim.x + threadIdx.x;
    {
        float v = graph[i];
        __nv_bfloat16 hi = __float2bfloat16(v);
        g_gh[i] = hi;
        g_gl[i] = __float2bfloat16(v - __bfloat162float(hi));
    }
    if (i < 192 * 64) {
        float v = W_hh[i];
        __nv_bfloat16 hi = __float2bfloat16(v);
        g_whh_h[i] = hi;
        g_whh_l[i] = __float2bfloat16(v - __bfloat162float(hi));
    }
    if (i < BHW) {
        int v  = i & (NV - 1);
        int hh = (i >> 10) & 63;
        float val = h0[hh * NV + v];
        __nv_bfloat16 hi = __float2bfloat16(val);
        g_hh[0][i] = hi;
        g_hl[0][i] = __float2bfloat16(val - __bfloat162float(hi));
    }
}

// t=0 prep from h0 directly. Grid (4, 8), 256 threads.
__global__ void prep_kernel(
    const float* __restrict__ x, const unsigned char* __restrict__ mask_raw,
    const float* __restrict__ h0,
    const float* __restrict__ W_init, const float* __restrict__ b_init,
    float* __restrict__ out_preds)
{
    int b = blockIdx.y;
    int v = blockIdx.x * 256 + threadIdx.x;
    float d = 0.f;
    #pragma unroll 16
    for (int hh = 0; hh < HID; hh++) d += W_init[hh] * h0[hh * NV + v];
    d += b_init[0];
    int xi = (b * NV + v) * NT + 0;
    int mode = g_mask_mode;
    bool m;
    if (mode == 0)      m = mask_raw[xi] != 0;
    else if (mode == 1) m = ((const int*)mask_raw)[xi] != 0;
    else                m = ((const float*)mask_raw)[xi] != 0.f;
    g_xh[b][v] = m ? x[xi] : d;
    out_preds[xi] = d;
}

// Final transpose: scratch [t][bhw] -> out_reprs [bhw][t]. 8192 blocks, 256 thr.
__global__ void __launch_bounds__(256) transpose_reprs_kernel(float* __restrict__ out) {
    __shared__ float sm[64][65];
    const int bhw0 = blockIdx.x * 64;
    const int c  = threadIdx.x & 63;
    const int r4 = threadIdx.x >> 6;
    #pragma unroll
    for (int i = 0; i < 16; i++) {
        int tt = r4 + 4 * i;
        sm[tt][c] = g_reprs[(size_t)tt * BHW + bhw0 + c];
    }
    __syncthreads();
    #pragma unroll
    for (int i = 0; i < 16; i++) {
        int row = r4 + 4 * i;
        out[(size_t)(bhw0 + row) * NT + c] = sm[c][row];
    }
}

// ---------------------------------------------------------------------------
// Step kernel: grid (16 w-tiles, 8 batches), 256 threads (8 warps).
// k-chunk = 128 (8 double-buffered iterations).
// ---------------------------------------------------------------------------
__global__ void __launch_bounds__(256) step_tc_kernel(int t, int cur,
    const float* __restrict__ x, const unsigned char* __restrict__ mask_raw,
    const float* __restrict__ ind_graph,
    const float* __restrict__ W_init, const float* __restrict__ b_init,
    const float* __restrict__ W_out,  const float* __restrict__ b_out,
    const float* __restrict__ W_ih,
    const float* __restrict__ b_ih,   const float* __restrict__ b_hh,
    float* __restrict__ out_imps, float* __restrict__ out_preds)
{
    extern __shared__ __align__(32) char smem[];
    const uint32_t sbase = (uint32_t)__cvta_generic_to_shared(smem);

    const int tid  = threadIdx.x;
    const int wid  = tid >> 5;
    const int wt   = blockIdx.x;
    const int b    = blockIdx.y;          // batch == m-tile
    const int w0   = wt * 64;
    const int m0   = b * 64;
    const int nxt  = cur ^ 1;

    float* hd   = (float*)(smem + OFF_HD);
    __nv_bfloat16* hdh = (__nv_bfloat16*)(smem + OFF_HDH);
    __nv_bfloat16* hdl = (__nv_bfloat16*)(smem + OFF_HDL);
    float* gd   = (float*)(smem + OFF_GD);
    float* hn   = (float*)(smem + OFF_HN);
    float* xg   = (float*)(smem + OFF_XG);
    float* part = (float*)(smem + OFF_PART);
    float* sx   = (float*)(smem + OFF_SX);
    float* smk  = (float*)(smem + OFF_SMK);
    float* gw   = (float*)(smem + OFF_GW);   // 7 x [64]

    // fill(kt): cp.async 4 bf16 tiles (Ah, Al, Bh, Bl), 64 rows x 128 cols, ld=136.
    auto fill = [&](int kt) {
        int buf = kt & 1;
        int v0  = kt * 128;
        const __nv_bfloat16* srcs[4] = {
            g_hh[cur] + (size_t)m0 * NV + v0,
            g_hl[cur] + (size_t)m0 * NV + v0,
            g_gh      + (size_t)w0 * NV + v0,
            g_gl      + (size_t)w0 * NV + v0 };
        const uint32_t dsts[4] = {
            sbase + OFF_AH(buf), sbase + OFF_AL(buf),
            sbase + OFF_BH(buf), sbase + OFF_BL(buf) };
        #pragma unroll
        for (int i = 0; i < 16; i++) {
            const int mat = i >> 2;
            int cc = (i & 3) * 256 + tid;       // 0..1023 16B chunks per matrix
            int row = cc >> 4, kc = cc & 15;
            cp_async16(dsts[mat] + row * (LDT * 2) + kc * 16,
                       srcs[mat] + row * NV + kc * 8);
        }
        cp_commit();
    };

    fill(0);

    // ---- stage gate weights/biases (per-hh) into smem ----
    if (tid < 64) {
        gw[tid]       = W_ih[tid];                        // Wr
        gw[64 + tid]  = W_ih[64 + tid];                   // Wz
        gw[128 + tid] = W_ih[128 + tid];                  // Wn
        gw[192 + tid] = b_ih[tid] + b_hh[tid];            // Br
        gw[256 + tid] = b_ih[64 + tid] + b_hh[64 + tid];  // Bz
        gw[320 + tid] = b_ih[128 + tid];                  // Bn
        gw[384 + tid] = b_hh[128 + tid];                  // Bhn
    }

    // ---- prefetch x/mask for t+1 (overlapped) ----
    if (tid >= 192 && t < NT - 1) {
        int w = tid - 192;
        int xi = (b * NV + w0 + w) * NT + (t + 1);
        int mode = g_mask_mode;
        bool m;
        if (mode == 0)      m = mask_raw[xi] != 0;
        else if (mode == 1) m = ((const int*)mask_raw)[xi] != 0;
        else                m = ((const float*)mask_raw)[xi] != 0.f;
        smk[w] = m ? 1.f : 0.f;
        sx[w]  = x[xi];
    }

    // ---- x_g[w] = sum_v g_xh[b][v] * ind_graph[w0+w][v] (overlaps tile-0) ----
    {
        int w = tid & 63, q = tid >> 6;
        const float4* ig = (const float4*)&ind_graph[(w0 + w) * NV + q * 256];
        const float4* xh = (const float4*)&g_xh[b][q * 256];
        float s = 0.f;
        #pragma unroll 16
        for (int j = 0; j < 64; j++) {
            float4 a = ig[j], c = xh[j];
            s += a.x * c.x + a.y * c.y + a.z * c.z + a.w * c.w;
        }
        part[q * 64 + w] = s;
    }
    __syncthreads();
    if (tid < 64)
        xg[tid] = part[tid] + part[64 + tid] + part[128 + tid] + part[192 + tid];

    // ---- GEMM: warp (wm = wid&3 -> m-tile, wn = wid>>2 -> 2 n-tiles) ----
    wmma::fragment<wmma::accumulator, 16, 16, 16, float> acc[2];
    wmma::fill_fragment(acc[0], 0.f);
    wmma::fill_fragment(acc[1], 0.f);
    const int wm = wid & 3, wn = wid >> 2;

    for (int kt = 0; kt < 8; kt++) {
        if (kt < 7) { fill(kt + 1); cp_wait1(); } else { cp_wait0(); }
        __syncthreads();                         // buffer kt ready
        const int buf = kt & 1;
        const __nv_bfloat16* Ah = (const __nv_bfloat16*)(smem + OFF_AH(buf));
        const __nv_bfloat16* Al = (const __nv_bfloat16*)(smem + OFF_AL(buf));
        const __nv_bfloat16* Bh = (const __nv_bfloat16*)(smem + OFF_BH(buf));
        const __nv_bfloat16* Bl = (const __nv_bfloat16*)(smem + OFF_BL(buf));
        #pragma unroll
        for (int ks = 0; ks < 8; ks++) {
            wmma::fragment<wmma::matrix_a, 16, 16, 16, __nv_bfloat16, wmma::row_major> fah, fal;
            wmma::load_matrix_sync(fah, Ah + wm * 16 * LDT + ks * 16, LDT);
            wmma::load_matrix_sync(fal, Al + wm * 16 * LDT + ks * 16, LDT);
            #pragma unroll
            for (int ni = 0; ni < 2; ni++) {
                wmma::fragment<wmma::matrix_b, 16, 16, 16, __nv_bfloat16, wmma::col_major> fbh, fbl;
                int boff = (wn * 2 + ni) * 16 * LDT + ks * 16;
                wmma::load_matrix_sync(fbh, Bh + boff, LDT);
                wmma::load_matrix_sync(fbl, Bl + boff, LDT);
                wmma::mma_sync(acc[ni], fah, fbh, acc[ni]);
                wmma::mma_sync(acc[ni], fah, fbl, acc[ni]);
                wmma::mma_sync(acc[ni], fal, fbh, acc[ni]);
            }
        }
        __syncthreads();                         // all reads done before refill
    }

    // ---- store h_diff (f32) into smem [64][72] (aliases dead buffers) ----
    wmma::store_matrix_sync(hd + wm * 16 * 72 + (wn * 2 + 0) * 16, acc[0], 72, wmma::mem_row_major);
    wmma::store_matrix_sync(hd + wm * 16 * 72 + (wn * 2 + 1) * 16, acc[1], 72, wmma::mem_row_major);
    __syncthreads();

    // ---- split h_diff -> bf16 hi/lo for the gate GEMM ----
    #pragma unroll
    for (int i = 0; i < 16; i++) {
        int idx = tid + i * 256;               // 4096
        int row = idx >> 6, col = idx & 63;
        float v = hd[row * 72 + col];
        __nv_bfloat16 hi = __float2bfloat16(v);
        hdh[row * 72 + col] = hi;
        hdl[row * 72 + col] = __float2bfloat16(v - __bfloat162float(hi));
    }
    __syncthreads();

    // ---- gates GEMM: gd[192 x 64] = W_hh · h_diff (W fragments from global) ----
    {
        const int gm = wid >> 1, gn = wid & 1;   // 3 m-tiles, 2 n-tiles per warp
        wmma::fragment<wmma::accumulator, 16, 16, 16, float> gacc[3][2];
        #pragma unroll
        for (int mi = 0; mi < 3; mi++)
            #pragma unroll
            for (int ni = 0; ni < 2; ni++) wmma::fill_fragment(gacc[mi][ni], 0.f);
        #pragma unroll
        for (int ks = 0; ks < 4; ks++) {
            wmma::fragment<wmma::matrix_b, 16, 16, 16, __nv_bfloat16, wmma::row_major> gbh[2], gbl[2];
            #pragma unroll
            for (int ni = 0; ni < 2; ni++) {
                int boff = ks * 16 * 72 + (gn * 2 + ni) * 16;
                wmma::load_matrix_sync(gbh[ni], hdh + boff, 72);
                wmma::load_matrix_sync(gbl[ni], hdl + boff, 72);
            }
            #pragma unroll
            for (int mi = 0; mi < 3; mi++) {
                wmma::fragment<wmma::matrix_a, 16, 16, 16, __nv_bfloat16, wmma::row_major> fah, fal;
                int aoff = (gm * 3 + mi) * 16 * 64 + ks * 16;
                wmma::load_matrix_sync(fah, g_whh_h + aoff, 64);
                wmma::load_matrix_sync(fal, g_whh_l + aoff, 64);
                #pragma unroll
                for (int ni = 0; ni < 2; ni++) {
                    wmma::mma_sync(gacc[mi][ni], fah, gbh[ni], gacc[mi][ni]);
                    wmma::mma_sync(gacc[mi][ni], fah, gbl[ni], gacc[mi][ni]);
                    wmma::mma_sync(gacc[mi][ni], fal, gbh[ni], gacc[mi][ni]);
                }
            }
        }
        #pragma unroll
        for (int mi = 0; mi < 3; mi++)
            #pragma unroll
            for (int ni = 0; ni < 2; ni++)
                wmma::store_matrix_sync(gd + (gm * 3 + mi) * 16 * 72 + (gn * 2 + ni) * 16,
                                        gacc[mi][ni], 72, wmma::mem_row_major);
    }
    __syncthreads();

    // ---- nonlinearity + state update: warp = 32 contiguous w (coalesced) ----
    {
        const int w = tid & 63;
        const int q = tid >> 6;
        float xgv = xg[w];
        #pragma unroll
        for (int k = 0; k < 16; k++) {
            int hh = q + 4 * k;
            float ar = gd[hh * 72 + w];
            float az = gd[(64 + hh) * 72 + w];
            float an = gd[(128 + hh) * 72 + w];
            float r = 0.5f + 0.5f * tanh_fast(0.5f * (ar + gw[hh] * xgv + gw[192 + hh]));
            float z = 0.5f + 0.5f * tanh_fast(0.5f * (az + gw[64 + hh] * xgv + gw[256 + hh]));
            float n = tanh_fast(gw[128 + hh] * xgv + gw[320 + hh] + r * (an + gw[384 + hh]));
            float hd_self = hd[hh * 72 + w];
            float hnew = (1.f - z) * n + z * hd_self;
            size_t si = (size_t)(m0 + hh) * NV + w0 + w;
            __nv_bfloat16 hi = __float2bfloat16(hnew);
            g_hh[nxt][si] = hi;
            g_hl[nxt][si] = __float2bfloat16(hnew - __bfloat162float(hi));
            g_reprs[(size_t)t * BHW + si] = hnew;     // coalesced 128B lines
            hn[hh * 72 + w] = hnew;
        }
    }
    __syncthreads();

    // ---- fused epilogue: imps(t), preds(t+1), g_xh(t+1) ----
    {
        int w = tid & 63, q = tid >> 6;
        float so = 0.f, si = 0.f;
        #pragma unroll
        for (int j = 0; j < 16; j++) {
            int hh = q * 16 + j;
            float hv = hn[hh * 72 + w];
            so += W_out[hh]  * hv;
            si += W_init[hh] * hv;
        }
        part[q * 64 + w]       = so;
        part[256 + q * 64 + w] = si;
    }
    __syncthreads();
    if (tid < 64) {
        int w = tid;
        float so = part[w] + part[64 + w] + part[128 + w] + part[192 + w];
        stcs(&out_imps[(b * NV + w0 + w) * NT + t], so + b_out[0]);
        if (t < NT - 1) {
            float si = part[256 + w] + part[320 + w] + part[384 + w] + part[448 + w];
            float d = si + b_init[0];
            int xi = (b * NV + w0 + w) * NT + (t + 1);
            g_xh[b][w0 + w] = (smk[w] != 0.f) ? sx[w] : d;
            stcs(&out_preds[xi], d);
        }
    }
}

// ---------------------------------------------------------------------------
extern "C" void kernel_launch(void* const* d_in, const int* in_sizes, int n_in,
                              void* d_out, int out_size) {
    const float* x          = (const float*)d_in[0];
    const unsigned char* mk = (const unsigned char*)d_in[1];
    const float* graph      = (const float*)d_in[2];
    const float* ind_graph  = (const float*)d_in[3];
    const float* h0         = (const float*)d_in[4];
    const float* W_init     = (const float*)d_in[5];
    const float* b_init     = (const float*)d_in[6];
    const float* W_out      = (const float*)d_in[7];
    const float* b_out      = (const float*)d_in[8];
    const float* W_ih       = (const float*)d_in[9];
    const float* W_hh       = (const float*)d_in[10];
    const float* b_ih       = (const float*)d_in[11];
    const float* b_hh       = (const float*)d_in[12];

    float* out_imps  = (float*)d_out;
    float* out_preds = out_imps + BSZ * NV * NT;
    float* out_reprs = out_preds + BSZ * NV * NT;

    cudaFuncSetAttribute(step_tc_kernel, cudaFuncAttributeMaxDynamicSharedMemorySize,
                         SMEM_TOTAL);

    detect_mask_kernel<<<1, 256>>>((const unsigned int*)mk);
    setup_kernel<<<NV * NV / 256, 256>>>(graph, W_hh, h0);
    prep_kernel<<<dim3(4, BSZ), 256>>>(x, mk, h0, W_init, b_init, out_preds);
    for (int t = 0; t < NT; t++) {
        step_tc_kernel<<<dim3(16, BSZ), 256, SMEM_TOTAL>>>(
            t, t & 1, x, mk, ind_graph,
            W_init, b_init, W_out, b_out, W_ih, b_ih, b_hh,
            out_imps, out_preds);
    }
    transpose_reprs_kernel<<<BHW / 64, 256>>>(out_reprs);
}

// round 15
// speedup vs baseline: 1.6824x; 1.2149x over previous
#include <cuda_runtime.h>
#include <cuda_bf16.h>
#include <mma.h>
#include <cstdint>

using namespace nvcuda;

#define BSZ 8
#define HID 64
#define NV  1024
#define NT  64
#define BHW (BSZ * HID * NV)

// bf16 hi/lo split state [buf][(b*64+hid)*NV + v]
__device__ __nv_bfloat16 g_hh[2][BHW];
__device__ __nv_bfloat16 g_hl[2][BHW];
__device__ __nv_bfloat16 g_gh[NV * NV];       // graph hi  [w][v]
__device__ __nv_bfloat16 g_gl[NV * NV];       // graph lo
__device__ __nv_bfloat16 g_whh_h[192 * 64];   // W_hh hi [gate][hid]
__device__ __nv_bfloat16 g_whh_l[192 * 64];
__device__ float g_xh[BSZ][NV];
__device__ float g_reprs[(size_t)NT * BHW];   // step-major staging for reprs
__device__ int   g_mask_mode;                 // 0=byte, 1=int32, 2=float32

// smem byte offsets. GEMM buffers: [64 rows][136 cols] bf16, k-chunk = 128.
#define LDT 136
#define TILE_B (64 * LDT * 2)                 // 17408
#define OFF_AH(b) ((b) * TILE_B)              // 0 .. 34816
#define OFF_AL(b) (34816 + (b) * TILE_B)      // 34816 .. 69632
#define OFF_BH(b) (69632 + (b) * TILE_B)      // 69632 .. 104448
#define OFF_BL(b) (104448 + (b) * TILE_B)     // 104448 .. 139264
// post-GEMM regions alias the dead GEMM buffers:
#define OFF_HD   0          // f32 [64][72]  = 18432
#define OFF_HDH  18432      // bf16 [64][72] = 9216
#define OFF_HDL  27648      // bf16 [64][72] = 9216
#define OFF_GD   36864      // f32 [192][72] = 55296 -> ends 92160
#define OFF_HN   92160      // f32 [64][72]  = 18432 -> ends 110592
// non-aliased tail:
#define OFF_XG   139264     // f32 [64]
#define OFF_PART 139520     // f32 [512]
#define OFF_SX   141568     // f32 [64]  x(t+1)
#define OFF_SMK  141824     // f32 [64]  mask(t+1) as 0/1
#define OFF_GW   142080     // f32 7 x [64]
#define OFF_SXH  144128     // f32 [1024] staged g_xh[b][:] (16B aligned)
#define SMEM_TOTAL 148224

// ---------------------------------------------------------------------------
__device__ __forceinline__ void cp_async16(uint32_t s, const void* g) {
    asm volatile("cp.async.ca.shared.global [%0], [%1], 16;" :: "r"(s), "l"(g));
}
__device__ __forceinline__ void cp_commit() { asm volatile("cp.async.commit_group;"); }
__device__ __forceinline__ void cp_wait0()  { asm volatile("cp.async.wait_group 0;"); }
__device__ __forceinline__ void cp_wait1()  { asm volatile("cp.async.wait_group 1;"); }
__device__ __forceinline__ void stcs(float* p, float v) {
    asm volatile("st.global.cs.f32 [%0], %1;" :: "l"(p), "f"(v));
}
__device__ __forceinline__ float tanh_fast(float x) {
    float y;
    asm("tanh.approx.f32 %0, %1;" : "=f"(y) : "f"(x));
    return y;
}

// ---------------------------------------------------------------------------
__global__ void detect_mask_kernel(const unsigned int* __restrict__ m) {
    __shared__ int viol_i, viol_f;
    if (threadIdx.x == 0) { viol_i = 0; viol_f = 0; }
    __syncthreads();
    int li = 0, lf = 0;
    const int nwords = (BSZ * NV * NT) / 4;
    for (int i = threadIdx.x; i < nwords; i += blockDim.x) {
        unsigned int w = m[i];
        if (w > 1u) li = 1;
        if (w != 0u && w != 0x3F800000u) lf = 1;
    }
    if (li) atomicOr(&viol_i, 1);
    if (lf) atomicOr(&viol_f, 1);
    __syncthreads();
    if (threadIdx.x == 0)
        g_mask_mode = (!viol_f) ? 2 : ((!viol_i) ? 1 : 0);
}

// Merged one-time setup: graph split, W_hh split, h0 init.
__global__ void setup_kernel(const float* __restrict__ graph,
                             const float* __restrict__ W_hh,
                             const float* __restrict__ h0) {
    int i = blockIdx.x * blockDim.x + threadIdx.x;
    {
        float v = graph[i];
        __nv_bfloat16 hi = __float2bfloat16(v);
        g_gh[i] = hi;
        g_gl[i] = __float2bfloat16(v - __bfloat162float(hi));
    }
    if (i < 192 * 64) {
        float v = W_hh[i];
        __nv_bfloat16 hi = __float2bfloat16(v);
        g_whh_h[i] = hi;
        g_whh_l[i] = __float2bfloat16(v - __bfloat162float(hi));
    }
    if (i < BHW) {
        int v  = i & (NV - 1);
        int hh = (i >> 10) & 63;
        float val = h0[hh * NV + v];
        __nv_bfloat16 hi = __float2bfloat16(val);
        g_hh[0][i] = hi;
        g_hl[0][i] = __float2bfloat16(val - __bfloat162float(hi));
    }
}

// t=0 prep from h0 directly. Grid (4, 8), 256 threads.
__global__ void prep_kernel(
    const float* __restrict__ x, const unsigned char* __restrict__ mask_raw,
    const float* __restrict__ h0,
    const float* __restrict__ W_init, const float* __restrict__ b_init,
    float* __restrict__ out_preds)
{
    int b = blockIdx.y;
    int v = blockIdx.x * 256 + threadIdx.x;
    float d = 0.f;
    #pragma unroll 16
    for (int hh = 0; hh < HID; hh++) d += W_init[hh] * h0[hh * NV + v];
    d += b_init[0];
    int xi = (b * NV + v) * NT + 0;
    int mode = g_mask_mode;
    bool m;
    if (mode == 0)      m = mask_raw[xi] != 0;
    else if (mode == 1) m = ((const int*)mask_raw)[xi] != 0;
    else                m = ((const float*)mask_raw)[xi] != 0.f;
    g_xh[b][v] = m ? x[xi] : d;
    out_preds[xi] = d;
}

// Final transpose: scratch [t][bhw] -> out_reprs [bhw][t]. 8192 blocks, 256 thr.
__global__ void __launch_bounds__(256) transpose_reprs_kernel(float* __restrict__ out) {
    __shared__ float sm[64][65];
    const int bhw0 = blockIdx.x * 64;
    const int c  = threadIdx.x & 63;
    const int r4 = threadIdx.x >> 6;
    #pragma unroll
    for (int i = 0; i < 16; i++) {
        int tt = r4 + 4 * i;
        sm[tt][c] = g_reprs[(size_t)tt * BHW + bhw0 + c];
    }
    __syncthreads();
    #pragma unroll
    for (int i = 0; i < 16; i++) {
        int row = r4 + 4 * i;
        out[(size_t)(bhw0 + row) * NT + c] = sm[c][row];
    }
}

// ---------------------------------------------------------------------------
// Step kernel: grid (16 w-tiles, 8 batches), 256 threads (8 warps).
// k-chunk = 128 (8 double-buffered iterations). Coalesced x_g.
// ---------------------------------------------------------------------------
__global__ void __launch_bounds__(256) step_tc_kernel(int t, int cur,
    const float* __restrict__ x, const unsigned char* __restrict__ mask_raw,
    const float* __restrict__ ind_graph,
    const float* __restrict__ W_init, const float* __restrict__ b_init,
    const float* __restrict__ W_out,  const float* __restrict__ b_out,
    const float* __restrict__ W_ih,
    const float* __restrict__ b_ih,   const float* __restrict__ b_hh,
    float* __restrict__ out_imps, float* __restrict__ out_preds)
{
    extern __shared__ __align__(32) char smem[];
    const uint32_t sbase = (uint32_t)__cvta_generic_to_shared(smem);

    const int tid  = threadIdx.x;
    const int wid  = tid >> 5;
    const int lane = tid & 31;
    const int wt   = blockIdx.x;
    const int b    = blockIdx.y;          // batch == m-tile
    const int w0   = wt * 64;
    const int m0   = b * 64;
    const int nxt  = cur ^ 1;

    float* hd   = (float*)(smem + OFF_HD);
    __nv_bfloat16* hdh = (__nv_bfloat16*)(smem + OFF_HDH);
    __nv_bfloat16* hdl = (__nv_bfloat16*)(smem + OFF_HDL);
    float* gd   = (float*)(smem + OFF_GD);
    float* hn   = (float*)(smem + OFF_HN);
    float* xg   = (float*)(smem + OFF_XG);
    float* part = (float*)(smem + OFF_PART);
    float* sx   = (float*)(smem + OFF_SX);
    float* smk  = (float*)(smem + OFF_SMK);
    float* gw   = (float*)(smem + OFF_GW);   // 7 x [64]
    float* sxh  = (float*)(smem + OFF_SXH);  // [1024]

    // fill(kt): cp.async 4 bf16 tiles (Ah, Al, Bh, Bl), 64 rows x 128 cols, ld=136.
    auto fill = [&](int kt) {
        int buf = kt & 1;
        int v0  = kt * 128;
        const __nv_bfloat16* srcs[4] = {
            g_hh[cur] + (size_t)m0 * NV + v0,
            g_hl[cur] + (size_t)m0 * NV + v0,
            g_gh      + (size_t)w0 * NV + v0,
            g_gl      + (size_t)w0 * NV + v0 };
        const uint32_t dsts[4] = {
            sbase + OFF_AH(buf), sbase + OFF_AL(buf),
            sbase + OFF_BH(buf), sbase + OFF_BL(buf) };
        #pragma unroll
        for (int i = 0; i < 16; i++) {
            const int mat = i >> 2;
            int cc = (i & 3) * 256 + tid;       // 0..1023 16B chunks per matrix
            int row = cc >> 4, kc = cc & 15;
            cp_async16(dsts[mat] + row * (LDT * 2) + kc * 16,
                       srcs[mat] + row * NV + kc * 8);
        }
        cp_commit();
    };

    fill(0);

    // ---- stage g_xh[b][:] into smem (coalesced float4) ----
    ((float4*)sxh)[tid] = ((const float4*)&g_xh[b][0])[tid];

    // ---- stage gate weights/biases (per-hh) into smem ----
    if (tid < 64) {
        gw[tid]       = W_ih[tid];                        // Wr
        gw[64 + tid]  = W_ih[64 + tid];                   // Wz
        gw[128 + tid] = W_ih[128 + tid];                  // Wn
        gw[192 + tid] = b_ih[tid] + b_hh[tid];            // Br
        gw[256 + tid] = b_ih[64 + tid] + b_hh[64 + tid];  // Bz
        gw[320 + tid] = b_ih[128 + tid];                  // Bn
        gw[384 + tid] = b_hh[128 + tid];                  // Bhn
    }

    // ---- prefetch x/mask for t+1 (overlapped) ----
    if (tid >= 192 && t < NT - 1) {
        int w = tid - 192;
        int xi = (b * NV + w0 + w) * NT + (t + 1);
        int mode = g_mask_mode;
        bool m;
        if (mode == 0)      m = mask_raw[xi] != 0;
        else if (mode == 1) m = ((const int*)mask_raw)[xi] != 0;
        else                m = ((const float*)mask_raw)[xi] != 0.f;
        smk[w] = m ? 1.f : 0.f;
        sx[w]  = x[xi];
    }
    __syncthreads();   // sxh staged

    // ---- x_g: warp owns 8 rows; lanes stride within row (coalesced) ----
    {
        float4 xv[8];
        #pragma unroll
        for (int j = 0; j < 8; j++) xv[j] = ((const float4*)sxh)[j * 32 + lane];
        const int row0 = wid * 8;
        #pragma unroll
        for (int rr = 0; rr < 8; rr++) {
            const float4* ig = (const float4*)&ind_graph[(size_t)(w0 + row0 + rr) * NV];
            float s = 0.f;
            #pragma unroll
            for (int j = 0; j < 8; j++) {
                float4 a = ig[j * 32 + lane];
                s += a.x * xv[j].x + a.y * xv[j].y + a.z * xv[j].z + a.w * xv[j].w;
            }
            s += __shfl_xor_sync(0xffffffffu, s, 16);
            s += __shfl_xor_sync(0xffffffffu, s, 8);
            s += __shfl_xor_sync(0xffffffffu, s, 4);
            s += __shfl_xor_sync(0xffffffffu, s, 2);
            s += __shfl_xor_sync(0xffffffffu, s, 1);
            if (lane == 0) xg[row0 + rr] = s;
        }
    }

    // ---- GEMM: warp (wm = wid&3 -> m-tile, wn = wid>>2 -> 2 n-tiles) ----
    wmma::fragment<wmma::accumulator, 16, 16, 16, float> acc[2];
    wmma::fill_fragment(acc[0], 0.f);
    wmma::fill_fragment(acc[1], 0.f);
    const int wm = wid & 3, wn = wid >> 2;

    for (int kt = 0; kt < 8; kt++) {
        if (kt < 7) { fill(kt + 1); cp_wait1(); } else { cp_wait0(); }
        __syncthreads();                         // buffer kt ready
        const int buf = kt & 1;
        const __nv_bfloat16* Ah = (const __nv_bfloat16*)(smem + OFF_AH(buf));
        const __nv_bfloat16* Al = (const __nv_bfloat16*)(smem + OFF_AL(buf));
        const __nv_bfloat16* Bh = (const __nv_bfloat16*)(smem + OFF_BH(buf));
        const __nv_bfloat16* Bl = (const __nv_bfloat16*)(smem + OFF_BL(buf));
        #pragma unroll
        for (int ks = 0; ks < 8; ks++) {
            wmma::fragment<wmma::matrix_a, 16, 16, 16, __nv_bfloat16, wmma::row_major> fah, fal;
            wmma::load_matrix_sync(fah, Ah + wm * 16 * LDT + ks * 16, LDT);
            wmma::load_matrix_sync(fal, Al + wm * 16 * LDT + ks * 16, LDT);
            #pragma unroll
            for (int ni = 0; ni < 2; ni++) {
                wmma::fragment<wmma::matrix_b, 16, 16, 16, __nv_bfloat16, wmma::col_major> fbh, fbl;
                int boff = (wn * 2 + ni) * 16 * LDT + ks * 16;
                wmma::load_matrix_sync(fbh, Bh + boff, LDT);
                wmma::load_matrix_sync(fbl, Bl + boff, LDT);
                wmma::mma_sync(acc[ni], fah, fbh, acc[ni]);
                wmma::mma_sync(acc[ni], fah, fbl, acc[ni]);
                wmma::mma_sync(acc[ni], fal, fbh, acc[ni]);
            }
        }
        __syncthreads();                         // all reads done before refill
    }

    // ---- store h_diff (f32) into smem [64][72] (aliases dead buffers) ----
    wmma::store_matrix_sync(hd + wm * 16 * 72 + (wn * 2 + 0) * 16, acc[0], 72, wmma::mem_row_major);
    wmma::store_matrix_sync(hd + wm * 16 * 72 + (wn * 2 + 1) * 16, acc[1], 72, wmma::mem_row_major);
    __syncthreads();

    // ---- split h_diff -> bf16 hi/lo for the gate GEMM ----
    #pragma unroll
    for (int i = 0; i < 16; i++) {
        int idx = tid + i * 256;               // 4096
        int row = idx >> 6, col = idx & 63;
        float v = hd[row * 72 + col];
        __nv_bfloat16 hi = __float2bfloat16(v);
        hdh[row * 72 + col] = hi;
        hdl[row * 72 + col] = __float2bfloat16(v - __bfloat162float(hi));
    }
    __syncthreads();

    // ---- gates GEMM: gd[192 x 64] = W_hh · h_diff (W fragments from global) ----
    {
        const int gm = wid >> 1, gn = wid & 1;   // 3 m-tiles, 2 n-tiles per warp
        wmma::fragment<wmma::accumulator, 16, 16, 16, float> gacc[3][2];
        #pragma unroll
        for (int mi = 0; mi < 3; mi++)
            #pragma unroll
            for (int ni = 0; ni < 2; ni++) wmma::fill_fragment(gacc[mi][ni], 0.f);
        #pragma unroll
        for (int ks = 0; ks < 4; ks++) {
            wmma::fragment<wmma::matrix_b, 16, 16, 16, __nv_bfloat16, wmma::row_major> gbh[2], gbl[2];
            #pragma unroll
            for (int ni = 0; ni < 2; ni++) {
                int boff = ks * 16 * 72 + (gn * 2 + ni) * 16;
                wmma::load_matrix_sync(gbh[ni], hdh + boff, 72);
                wmma::load_matrix_sync(gbl[ni], hdl + boff, 72);
            }
            #pragma unroll
            for (int mi = 0; mi < 3; mi++) {
                wmma::fragment<wmma::matrix_a, 16, 16, 16, __nv_bfloat16, wmma::row_major> fah, fal;
                int aoff = (gm * 3 + mi) * 16 * 64 + ks * 16;
                wmma::load_matrix_sync(fah, g_whh_h + aoff, 64);
                wmma::load_matrix_sync(fal, g_whh_l + aoff, 64);
                #pragma unroll
                for (int ni = 0; ni < 2; ni++) {
                    wmma::mma_sync(gacc[mi][ni], fah, gbh[ni], gacc[mi][ni]);
                    wmma::mma_sync(gacc[mi][ni], fah, gbl[ni], gacc[mi][ni]);
                    wmma::mma_sync(gacc[mi][ni], fal, gbh[ni], gacc[mi][ni]);
                }
            }
        }
        #pragma unroll
        for (int mi = 0; mi < 3; mi++)
            #pragma unroll
            for (int ni = 0; ni < 2; ni++)
                wmma::store_matrix_sync(gd + (gm * 3 + mi) * 16 * 72 + (gn * 2 + ni) * 16,
                                        gacc[mi][ni], 72, wmma::mem_row_major);
    }
    __syncthreads();

    // ---- nonlinearity + state update: warp = 32 contiguous w (coalesced) ----
    {
        const int w = tid & 63;
        const int q = tid >> 6;
        float xgv = xg[w];
        #pragma unroll
        for (int k = 0; k < 16; k++) {
            int hh = q + 4 * k;
            float ar = gd[hh * 72 + w];
            float az = gd[(64 + hh) * 72 + w];
            float an = gd[(128 + hh) * 72 + w];
            float r = 0.5f + 0.5f * tanh_fast(0.5f * (ar + gw[hh] * xgv + gw[192 + hh]));
            float z = 0.5f + 0.5f * tanh_fast(0.5f * (az + gw[64 + hh] * xgv + gw[256 + hh]));
            float n = tanh_fast(gw[128 + hh] * xgv + gw[320 + hh] + r * (an + gw[384 + hh]));
            float hd_self = hd[hh * 72 + w];
            float hnew = (1.f - z) * n + z * hd_self;
            size_t si = (size_t)(m0 + hh) * NV + w0 + w;
            __nv_bfloat16 hi = __float2bfloat16(hnew);
            g_hh[nxt][si] = hi;
            g_hl[nxt][si] = __float2bfloat16(hnew - __bfloat162float(hi));
            g_reprs[(size_t)t * BHW + si] = hnew;     // coalesced 128B lines
            hn[hh * 72 + w] = hnew;
        }
    }
    __syncthreads();

    // ---- fused epilogue: imps(t), preds(t+1), g_xh(t+1) ----
    {
        int w = tid & 63, q = tid >> 6;
        float so = 0.f, si = 0.f;
        #pragma unroll
        for (int j = 0; j < 16; j++) {
            int hh = q * 16 + j;
            float hv = hn[hh * 72 + w];
            so += W_out[hh]  * hv;
            si += W_init[hh] * hv;
        }
        part[q * 64 + w]       = so;
        part[256 + q * 64 + w] = si;
    }
    __syncthreads();
    if (tid < 64) {
        int w = tid;
        float so = part[w] + part[64 + w] + part[128 + w] + part[192 + w];
        stcs(&out_imps[(b * NV + w0 + w) * NT + t], so + b_out[0]);
        if (t < NT - 1) {
            float si = part[256 + w] + part[320 + w] + part[384 + w] + part[448 + w];
            float d = si + b_init[0];
            int xi = (b * NV + w0 + w) * NT + (t + 1);
            g_xh[b][w0 + w] = (smk[w] != 0.f) ? sx[w] : d;
            stcs(&out_preds[xi], d);
        }
    }
}

// ---------------------------------------------------------------------------
extern "C" void kernel_launch(void* const* d_in, const int* in_sizes, int n_in,
                              void* d_out, int out_size) {
    const float* x          = (const float*)d_in[0];
    const unsigned char* mk = (const unsigned char*)d_in[1];
    const float* graph      = (const float*)d_in[2];
    const float* ind_graph  = (const float*)d_in[3];
    const float* h0         = (const float*)d_in[4];
    const float* W_init     = (const float*)d_in[5];
    const float* b_init     = (const float*)d_in[6];
    const float* W_out      = (const float*)d_in[7];
    const float* b_out      = (const float*)d_in[8];
    const float* W_ih       = (const float*)d_in[9];
    const float* W_hh       = (const float*)d_in[10];
    const float* b_ih       = (const float*)d_in[11];
    const float* b_hh       = (const float*)d_in[12];

    float* out_imps  = (float*)d_out;
    float* out_preds = out_imps + BSZ * NV * NT;
    float* out_reprs = out_preds + BSZ * NV * NT;

    cudaFuncSetAttribute(step_tc_kernel, cudaFuncAttributeMaxDynamicSharedMemorySize,
                         SMEM_TOTAL);

    detect_mask_kernel<<<1, 256>>>((const unsigned int*)mk);
    setup_kernel<<<NV * NV / 256, 256>>>(graph, W_hh, h0);
    prep_kernel<<<dim3(4, BSZ), 256>>>(x, mk, h0, W_init, b_init, out_preds);
    for (int t = 0; t < NT; t++) {
        step_tc_kernel<<<dim3(16, BSZ), 256, SMEM_TOTAL>>>(
            t, t & 1, x, mk, ind_graph,
            W_init, b_init, W_out, b_out, W_ih, b_ih, b_hh,
            out_imps, out_preds);
    }
    transpose_reprs_kernel<<<BHW / 64, 256>>>(out_reprs);
}

// round 16
// speedup vs baseline: 1.8211x; 1.0824x over previous
#include <cuda_runtime.h>
#include <cuda_bf16.h>
#include <mma.h>
#include <cstdint>

using namespace nvcuda;

#define BSZ 8
#define HID 64
#define NV  1024
#define NT  64
#define BHW (BSZ * HID * NV)

// bf16 hi/lo split state [buf][(b*64+hid)*NV + v]
__device__ __nv_bfloat16 g_hh[2][BHW];
__device__ __nv_bfloat16 g_hl[2][BHW];
__device__ __nv_bfloat16 g_gh[NV * NV];       // graph hi  [w][v]
__device__ __nv_bfloat16 g_gl[NV * NV];       // graph lo
__device__ __nv_bfloat16 g_whh_h[192 * 64];   // W_hh hi [gate][hid]
__device__ __nv_bfloat16 g_whh_l[192 * 64];
__device__ float g_xh[BSZ][NV];
__device__ float g_reprs[(size_t)NT * BHW];   // step-major staging for reprs
__device__ int   g_mask_mode;                 // 0=byte, 1=int32, 2=float32

// smem byte offsets. GEMM buffers: [64 rows][136 cols] bf16, k-chunk = 128.
#define LDT 136
#define TILE_B (64 * LDT * 2)                 // 17408
#define OFF_AH(b) ((b) * TILE_B)              // 0 .. 34816
#define OFF_AL(b) (34816 + (b) * TILE_B)      // 34816 .. 69632
#define OFF_BH(b) (69632 + (b) * TILE_B)      // 69632 .. 104448
#define OFF_BL(b) (104448 + (b) * TILE_B)     // 104448 .. 139264
// post-GEMM regions alias the dead GEMM buffers:
#define OFF_P(k) ((k) * 18432)                // 4 k-split partials, f32 [64][72]
#define OFF_HD   OFF_P(0)                     // reduced h_diff (in place)
#define OFF_HN   OFF_P(1)                     // h_new, after reduction
#define OFF_HDH  73728                        // bf16 [64][72]
#define OFF_HDL  82944                        // bf16 [64][72]
#define OFF_GD   92160                        // f32 [192][72] -> ends 147456
// non-aliased tail:
#define OFF_XG   147456     // f32 [64]
#define OFF_PART 147712     // f32 [512]
#define OFF_SX   149760     // f32 [64]  x(t+1)
#define OFF_SMK  150016     // f32 [64]  mask(t+1) as 0/1
#define OFF_GW   150272     // f32 7 x [64]
#define OFF_SXH  152064     // f32 [1024] staged g_xh[b][:]
#define SMEM_TOTAL 156160

// ---------------------------------------------------------------------------
__device__ __forceinline__ void cp_async16(uint32_t s, const void* g) {
    asm volatile("cp.async.ca.shared.global [%0], [%1], 16;" :: "r"(s), "l"(g));
}
__device__ __forceinline__ void cp_commit() { asm volatile("cp.async.commit_group;"); }
__device__ __forceinline__ void cp_wait0()  { asm volatile("cp.async.wait_group 0;"); }
__device__ __forceinline__ void cp_wait1()  { asm volatile("cp.async.wait_group 1;"); }
__device__ __forceinline__ void stcs(float* p, float v) {
    asm volatile("st.global.cs.f32 [%0], %1;" :: "l"(p), "f"(v));
}
__device__ __forceinline__ float tanh_fast(float x) {
    float y;
    asm("tanh.approx.f32 %0, %1;" : "=f"(y) : "f"(x));
    return y;
}

// ---------------------------------------------------------------------------
__global__ void detect_mask_kernel(const unsigned int* __restrict__ m) {
    __shared__ int viol_i, viol_f;
    if (threadIdx.x == 0) { viol_i = 0; viol_f = 0; }
    __syncthreads();
    int li = 0, lf = 0;
    const int nwords = (BSZ * NV * NT) / 4;
    for (int i = threadIdx.x; i < nwords; i += blockDim.x) {
        unsigned int w = m[i];
        if (w > 1u) li = 1;
        if (w != 0u && w != 0x3F800000u) lf = 1;
    }
    if (li) atomicOr(&viol_i, 1);
    if (lf) atomicOr(&viol_f, 1);
    __syncthreads();
    if (threadIdx.x == 0)
        g_mask_mode = (!viol_f) ? 2 : ((!viol_i) ? 1 : 0);
}

// Merged one-time setup: graph split, W_hh split, h0 init.
__global__ void setup_kernel(const float* __restrict__ graph,
                             const float* __restrict__ W_hh,
                             const float* __restrict__ h0) {
    int i = blockIdx.x * blockDim.x + threadIdx.x;
    {
        float v = graph[i];
        __nv_bfloat16 hi = __float2bfloat16(v);
        g_gh[i] = hi;
        g_gl[i] = __float2bfloat16(v - __bfloat162float(hi));
    }
    if (i < 192 * 64) {
        float v = W_hh[i];
        __nv_bfloat16 hi = __float2bfloat16(v);
        g_whh_h[i] = hi;
        g_whh_l[i] = __float2bfloat16(v - __bfloat162float(hi));
    }
    if (i < BHW) {
        int v  = i & (NV - 1);
        int hh = (i >> 10) & 63;
        float val = h0[hh * NV + v];
        __nv_bfloat16 hi = __float2bfloat16(val);
        g_hh[0][i] = hi;
        g_hl[0][i] = __float2bfloat16(val - __bfloat162float(hi));
    }
}

// t=0 prep from h0 directly. Grid (4, 8), 256 threads.
__global__ void prep_kernel(
    const float* __restrict__ x, const unsigned char* __restrict__ mask_raw,
    const float* __restrict__ h0,
    const float* __restrict__ W_init, const float* __restrict__ b_init,
    float* __restrict__ out_preds)
{
    int b = blockIdx.y;
    int v = blockIdx.x * 256 + threadIdx.x;
    float d = 0.f;
    #pragma unroll 16
    for (int hh = 0; hh < HID; hh++) d += W_init[hh] * h0[hh * NV + v];
    d += b_init[0];
    int xi = (b * NV + v) * NT + 0;
    int mode = g_mask_mode;
    bool m;
    if (mode == 0)      m = mask_raw[xi] != 0;
    else if (mode == 1) m = ((const int*)mask_raw)[xi] != 0;
    else                m = ((const float*)mask_raw)[xi] != 0.f;
    g_xh[b][v] = m ? x[xi] : d;
    out_preds[xi] = d;
}

// Final transpose: scratch [t][bhw] -> out_reprs [bhw][t]. 8192 blocks, 256 thr.
__global__ void __launch_bounds__(256) transpose_reprs_kernel(float* __restrict__ out) {
    __shared__ float sm[64][65];
    const int bhw0 = blockIdx.x * 64;
    const int c  = threadIdx.x & 63;
    const int r4 = threadIdx.x >> 6;
    #pragma unroll
    for (int i = 0; i < 16; i++) {
        int tt = r4 + 4 * i;
        sm[tt][c] = g_reprs[(size_t)tt * BHW + bhw0 + c];
    }
    __syncthreads();
    #pragma unroll
    for (int i = 0; i < 16; i++) {
        int row = r4 + 4 * i;
        out[(size_t)(bhw0 + row) * NT + c] = sm[c][row];
    }
}

// ---------------------------------------------------------------------------
// Step kernel: grid (16 w-tiles, 8 batches), 256 threads (8 warps).
// k-chunk = 128, k-split GEMM: warp = (k-quarter, m-half) computing 32x64
// partial; fused reduce+split pass afterwards.
// ---------------------------------------------------------------------------
__global__ void __launch_bounds__(256) step_tc_kernel(int t, int cur,
    const float* __restrict__ x, const unsigned char* __restrict__ mask_raw,
    const float* __restrict__ ind_graph,
    const float* __restrict__ W_init, const float* __restrict__ b_init,
    const float* __restrict__ W_out,  const float* __restrict__ b_out,
    const float* __restrict__ W_ih,
    const float* __restrict__ b_ih,   const float* __restrict__ b_hh,
    float* __restrict__ out_imps, float* __restrict__ out_preds)
{
    extern __shared__ __align__(32) char smem[];
    const uint32_t sbase = (uint32_t)__cvta_generic_to_shared(smem);

    const int tid  = threadIdx.x;
    const int wid  = tid >> 5;
    const int lane = tid & 31;
    const int wt   = blockIdx.x;
    const int b    = blockIdx.y;          // batch == m-tile
    const int w0   = wt * 64;
    const int m0   = b * 64;
    const int nxt  = cur ^ 1;

    float* hd   = (float*)(smem + OFF_HD);
    __nv_bfloat16* hdh = (__nv_bfloat16*)(smem + OFF_HDH);
    __nv_bfloat16* hdl = (__nv_bfloat16*)(smem + OFF_HDL);
    float* gd   = (float*)(smem + OFF_GD);
    float* hn   = (float*)(smem + OFF_HN);
    float* xg   = (float*)(smem + OFF_XG);
    float* part = (float*)(smem + OFF_PART);
    float* sx   = (float*)(smem + OFF_SX);
    float* smk  = (float*)(smem + OFF_SMK);
    float* gw   = (float*)(smem + OFF_GW);   // 7 x [64]
    float* sxh  = (float*)(smem + OFF_SXH);  // [1024]

    // fill(kt): cp.async 4 bf16 tiles (Ah, Al, Bh, Bl), 64 rows x 128 cols, ld=136.
    auto fill = [&](int kt) {
        int buf = kt & 1;
        int v0  = kt * 128;
        const __nv_bfloat16* srcs[4] = {
            g_hh[cur] + (size_t)m0 * NV + v0,
            g_hl[cur] + (size_t)m0 * NV + v0,
            g_gh      + (size_t)w0 * NV + v0,
            g_gl      + (size_t)w0 * NV + v0 };
        const uint32_t dsts[4] = {
            sbase + OFF_AH(buf), sbase + OFF_AL(buf),
            sbase + OFF_BH(buf), sbase + OFF_BL(buf) };
        #pragma unroll
        for (int i = 0; i < 16; i++) {
            const int mat = i >> 2;
            int cc = (i & 3) * 256 + tid;       // 0..1023 16B chunks per matrix
            int row = cc >> 4, kc = cc & 15;
            cp_async16(dsts[mat] + row * (LDT * 2) + kc * 16,
                       srcs[mat] + row * NV + kc * 8);
        }
        cp_commit();
    };

    fill(0);

    // ---- stage g_xh[b][:] into smem (coalesced float4) ----
    ((float4*)sxh)[tid] = ((const float4*)&g_xh[b][0])[tid];

    // ---- stage gate weights/biases (per-hh) into smem ----
    if (tid < 64) {
        gw[tid]       = W_ih[tid];                        // Wr
        gw[64 + tid]  = W_ih[64 + tid];                   // Wz
        gw[128 + tid] = W_ih[128 + tid];                  // Wn
        gw[192 + tid] = b_ih[tid] + b_hh[tid];            // Br
        gw[256 + tid] = b_ih[64 + tid] + b_hh[64 + tid];  // Bz
        gw[320 + tid] = b_ih[128 + tid];                  // Bn
        gw[384 + tid] = b_hh[128 + tid];                  // Bhn
    }

    // ---- prefetch x/mask for t+1 (overlapped) ----
    if (tid >= 192 && t < NT - 1) {
        int w = tid - 192;
        int xi = (b * NV + w0 + w) * NT + (t + 1);
        int mode = g_mask_mode;
        bool m;
        if (mode == 0)      m = mask_raw[xi] != 0;
        else if (mode == 1) m = ((const int*)mask_raw)[xi] != 0;
        else                m = ((const float*)mask_raw)[xi] != 0.f;
        smk[w] = m ? 1.f : 0.f;
        sx[w]  = x[xi];
    }
    __syncthreads();   // sxh staged

    // ---- x_g: warp owns 8 rows; lanes stride within row (coalesced) ----
    {
        float4 xv[8];
        #pragma unroll
        for (int j = 0; j < 8; j++) xv[j] = ((const float4*)sxh)[j * 32 + lane];
        const int row0 = wid * 8;
        #pragma unroll
        for (int rr = 0; rr < 8; rr++) {
            const float4* ig = (const float4*)&ind_graph[(size_t)(w0 + row0 + rr) * NV];
            float s = 0.f;
            #pragma unroll
            for (int j = 0; j < 8; j++) {
                float4 a = ig[j * 32 + lane];
                s += a.x * xv[j].x + a.y * xv[j].y + a.z * xv[j].z + a.w * xv[j].w;
            }
            s += __shfl_xor_sync(0xffffffffu, s, 16);
            s += __shfl_xor_sync(0xffffffffu, s, 8);
            s += __shfl_xor_sync(0xffffffffu, s, 4);
            s += __shfl_xor_sync(0xffffffffu, s, 2);
            s += __shfl_xor_sync(0xffffffffu, s, 1);
            if (lane == 0) xg[row0 + rr] = s;
        }
    }

    // ---- GEMM, k-split: warp (kq = wid>>1, mh = wid&1) -> 32m x 64n partial
    //      over ks = 2*kq .. 2*kq+1 of each k-chunk.
    wmma::fragment<wmma::accumulator, 16, 16, 16, float> acc[2][4];
    #pragma unroll
    for (int mi = 0; mi < 2; mi++)
        #pragma unroll
        for (int ni = 0; ni < 4; ni++) wmma::fill_fragment(acc[mi][ni], 0.f);
    const int kq = wid >> 1, mh = wid & 1;

    for (int kt = 0; kt < 8; kt++) {
        if (kt < 7) { fill(kt + 1); cp_wait1(); } else { cp_wait0(); }
        __syncthreads();                         // buffer kt ready
        const int buf = kt & 1;
        const __nv_bfloat16* Ah = (const __nv_bfloat16*)(smem + OFF_AH(buf));
        const __nv_bfloat16* Al = (const __nv_bfloat16*)(smem + OFF_AL(buf));
        const __nv_bfloat16* Bh = (const __nv_bfloat16*)(smem + OFF_BH(buf));
        const __nv_bfloat16* Bl = (const __nv_bfloat16*)(smem + OFF_BL(buf));
        #pragma unroll
        for (int kss = 0; kss < 2; kss++) {
            const int ks = kq * 2 + kss;
            wmma::fragment<wmma::matrix_a, 16, 16, 16, __nv_bfloat16, wmma::row_major> fah[2], fal[2];
            wmma::fragment<wmma::matrix_b, 16, 16, 16, __nv_bfloat16, wmma::col_major> fbh[4], fbl[4];
            #pragma unroll
            for (int mi = 0; mi < 2; mi++) {
                int aoff = (mh * 32 + mi * 16) * LDT + ks * 16;
                wmma::load_matrix_sync(fah[mi], Ah + aoff, LDT);
                wmma::load_matrix_sync(fal[mi], Al + aoff, LDT);
            }
            #pragma unroll
            for (int ni = 0; ni < 4; ni++) {
                int boff = ni * 16 * LDT + ks * 16;
                wmma::load_matrix_sync(fbh[ni], Bh + boff, LDT);
                wmma::load_matrix_sync(fbl[ni], Bl + boff, LDT);
            }
            #pragma unroll
            for (int mi = 0; mi < 2; mi++)
                #pragma unroll
                for (int ni = 0; ni < 4; ni++) {
                    wmma::mma_sync(acc[mi][ni], fah[mi], fbh[ni], acc[mi][ni]);
                    wmma::mma_sync(acc[mi][ni], fah[mi], fbl[ni], acc[mi][ni]);
                    wmma::mma_sync(acc[mi][ni], fal[mi], fbh[ni], acc[mi][ni]);
                }
        }
        __syncthreads();                         // all reads done before refill
    }

    // ---- store k-partials into smem (alias dead buffers) ----
    {
        float* P = (float*)(smem + OFF_P(kq));
        #pragma unroll
        for (int mi = 0; mi < 2; mi++)
            #pragma unroll
            for (int ni = 0; ni < 4; ni++)
                wmma::store_matrix_sync(P + (mh * 32 + mi * 16) * 72 + ni * 16,
                                        acc[mi][ni], 72, wmma::mem_row_major);
    }
    __syncthreads();

    // ---- fused k-reduce + bf16 hi/lo split ----
    {
        const float* P1 = (const float*)(smem + OFF_P(1));
        const float* P2 = (const float*)(smem + OFF_P(2));
        const float* P3 = (const float*)(smem + OFF_P(3));
        #pragma unroll
        for (int i = 0; i < 16; i++) {
            int idx = tid + i * 256;               // 4096
            int row = idx >> 6, col = idx & 63;
            int e = row * 72 + col;
            float v = hd[e] + P1[e] + P2[e] + P3[e];
            hd[e] = v;                              // in place (P0)
            __nv_bfloat16 hi = __float2bfloat16(v);
            hdh[e] = hi;
            hdl[e] = __float2bfloat16(v - __bfloat162float(hi));
        }
    }
    __syncthreads();

    // ---- gates GEMM: gd[192 x 64] = W_hh · h_diff (W fragments from global) ----
    {
        const int gm = wid >> 1, gn = wid & 1;   // 3 m-tiles, 2 n-tiles per warp
        wmma::fragment<wmma::accumulator, 16, 16, 16, float> gacc[3][2];
        #pragma unroll
        for (int mi = 0; mi < 3; mi++)
            #pragma unroll
            for (int ni = 0; ni < 2; ni++) wmma::fill_fragment(gacc[mi][ni], 0.f);
        #pragma unroll
        for (int ks = 0; ks < 4; ks++) {
            wmma::fragment<wmma::matrix_b, 16, 16, 16, __nv_bfloat16, wmma::row_major> gbh[2], gbl[2];
            #pragma unroll
            for (int ni = 0; ni < 2; ni++) {
                int boff = ks * 16 * 72 + (gn * 2 + ni) * 16;
                wmma::load_matrix_sync(gbh[ni], hdh + boff, 72);
                wmma::load_matrix_sync(gbl[ni], hdl + boff, 72);
            }
            #pragma unroll
            for (int mi = 0; mi < 3; mi++) {
                wmma::fragment<wmma::matrix_a, 16, 16, 16, __nv_bfloat16, wmma::row_major> fah, fal;
                int aoff = (gm * 3 + mi) * 16 * 64 + ks * 16;
                wmma::load_matrix_sync(fah, g_whh_h + aoff, 64);
                wmma::load_matrix_sync(fal, g_whh_l + aoff, 64);
                #pragma unroll
                for (int ni = 0; ni < 2; ni++) {
                    wmma::mma_sync(gacc[mi][ni], fah, gbh[ni], gacc[mi][ni]);
                    wmma::mma_sync(gacc[mi][ni], fah, gbl[ni], gacc[mi][ni]);
                    wmma::mma_sync(gacc[mi][ni], fal, gbh[ni], gacc[mi][ni]);
                }
            }
        }
        #pragma unroll
        for (int mi = 0; mi < 3; mi++)
            #pragma unroll
            for (int ni = 0; ni < 2; ni++)
                wmma::store_matrix_sync(gd + (gm * 3 + mi) * 16 * 72 + (gn * 2 + ni) * 16,
                                        gacc[mi][ni], 72, wmma::mem_row_major);
    }
    __syncthreads();

    // ---- nonlinearity + state update: warp = 32 contiguous w (coalesced) ----
    {
        const int w = tid & 63;
        const int q = tid >> 6;
        float xgv = xg[w];
        #pragma unroll
        for (int k = 0; k < 16; k++) {
            int hh = q + 4 * k;
            float ar = gd[hh * 72 + w];
            float az = gd[(64 + hh) * 72 + w];
            float an = gd[(128 + hh) * 72 + w];
            float r = 0.5f + 0.5f * tanh_fast(0.5f * (ar + gw[hh] * xgv + gw[192 + hh]));
            float z = 0.5f + 0.5f * tanh_fast(0.5f * (az + gw[64 + hh] * xgv + gw[256 + hh]));
            float n = tanh_fast(gw[128 + hh] * xgv + gw[320 + hh] + r * (an + gw[384 + hh]));
            float hd_self = hd[hh * 72 + w];
            float hnew = (1.f - z) * n + z * hd_self;
            size_t si = (size_t)(m0 + hh) * NV + w0 + w;
            __nv_bfloat16 hi = __float2bfloat16(hnew);
            g_hh[nxt][si] = hi;
            g_hl[nxt][si] = __float2bfloat16(hnew - __bfloat162float(hi));
            g_reprs[(size_t)t * BHW + si] = hnew;     // coalesced 128B lines
            hn[hh * 72 + w] = hnew;
        }
    }
    __syncthreads();

    // ---- fused epilogue: imps(t), preds(t+1), g_xh(t+1) ----
    {
        int w = tid & 63, q = tid >> 6;
        float so = 0.f, si = 0.f;
        #pragma unroll
        for (int j = 0; j < 16; j++) {
            int hh = q * 16 + j;
            float hv = hn[hh * 72 + w];
            so += W_out[hh]  * hv;
            si += W_init[hh] * hv;
        }
        part[q * 64 + w]       = so;
        part[256 + q * 64 + w] = si;
    }
    __syncthreads();
    if (tid < 64) {
        int w = tid;
        float so = part[w] + part[64 + w] + part[128 + w] + part[192 + w];
        stcs(&out_imps[(b * NV + w0 + w) * NT + t], so + b_out[0]);
        if (t < NT - 1) {
            float si = part[256 + w] + part[320 + w] + part[384 + w] + part[448 + w];
            float d = si + b_init[0];
            int xi = (b * NV + w0 + w) * NT + (t + 1);
            g_xh[b][w0 + w] = (smk[w] != 0.f) ? sx[w] : d;
            stcs(&out_preds[xi], d);
        }
    }
}

// ---------------------------------------------------------------------------
extern "C" void kernel_launch(void* const* d_in, const int* in_sizes, int n_in,
                              void* d_out, int out_size) {
    const float* x          = (const float*)d_in[0];
    const unsigned char* mk = (const unsigned char*)d_in[1];
    const float* graph      = (const float*)d_in[2];
    const float* ind_graph  = (const float*)d_in[3];
    const float* h0         = (const float*)d_in[4];
    const float* W_init     = (const float*)d_in[5];
    const float* b_init     = (const float*)d_in[6];
    const float* W_out      = (const float*)d_in[7];
    const float* b_out      = (const float*)d_in[8];
    const float* W_ih       = (const float*)d_in[9];
    const float* W_hh       = (const float*)d_in[10];
    const float* b_ih       = (const float*)d_in[11];
    const float* b_hh       = (const float*)d_in[12];

    float* out_imps  = (float*)d_out;
    float* out_preds = out_imps + BSZ * NV * NT;
    float* out_reprs = out_preds + BSZ * NV * NT;

    cudaFuncSetAttribute(step_tc_kernel, cudaFuncAttributeMaxDynamicSharedMemorySize,
                         SMEM_TOTAL);

    detect_mask_kernel<<<1, 256>>>((const unsigned int*)mk);
    setup_kernel<<<NV * NV / 256, 256>>>(graph, W_hh, h0);
    prep_kernel<<<dim3(4, BSZ), 256>>>(x, mk, h0, W_init, b_init, out_preds);
    for (int t = 0; t < NT; t++) {
        step_tc_kernel<<<dim3(16, BSZ), 256, SMEM_TOTAL>>>(
            t, t & 1, x, mk, ind_graph,
            W_init, b_init, W_out, b_out, W_ih, b_ih, b_hh,
            out_imps, out_preds);
    }
    transpose_reprs_kernel<<<BHW / 64, 256>>>(out_reprs);
}